// round 4
// baseline (speedup 1.0000x reference)
#include <cuda_runtime.h>
#include <cuda_bf16.h>
#include <cstdint>

// Problem constants
#define BB 2
#define SS 2048
#define EE 1024
#define HH 16
#define DD 64
#define RR 16
#define BH (BB*HH)          // 32
#define NQK (HH*DD)         // 1024
#define NTOT (2*NQK + HH*RR) // 2304
#define MROWS (BB*SS)       // 4096

// ---------------- device scratch ----------------
__device__ uint32_t g_Wall[EE * NTOT];       // packed [E][2304], pre-converted tf32
__device__ float g_ball[NTOT];
__device__ float g_q[BH * SS * DD];          // (b,h,s,d)
__device__ float g_k[BH * SS * DD];
__device__ float g_vd[BH * SS * RR];
__device__ float g_v[BH * SS * DD];

// ---------------- tf32 helpers ----------------
__device__ __forceinline__ uint32_t f2tf(float f) {
    uint32_t r;
    asm("cvt.rna.tf32.f32 %0, %1;" : "=r"(r) : "f"(f));
    return r;
}

__device__ __forceinline__ float ex2(float x) {
    float r;
    asm("ex2.approx.f32 %0, %1;" : "=f"(r) : "f"(x));
    return r;
}

__device__ __forceinline__ void mma_tf32(float c[4], const uint32_t a[4], uint32_t b0, uint32_t b1) {
    asm volatile(
        "mma.sync.aligned.m16n8k8.row.col.f32.tf32.tf32.f32 "
        "{%0,%1,%2,%3}, {%4,%5,%6,%7}, {%8,%9}, {%0,%1,%2,%3};"
        : "+f"(c[0]), "+f"(c[1]), "+f"(c[2]), "+f"(c[3])
        : "r"(a[0]), "r"(a[1]), "r"(a[2]), "r"(a[3]), "r"(b0), "r"(b1));
}

// ---------------- pack weights (now converts to tf32) ----------------
__global__ void pack_kernel(const float* __restrict__ Wq, const float* __restrict__ bq,
                            const float* __restrict__ Wk, const float* __restrict__ bk,
                            const float* __restrict__ Wvd, const float* __restrict__ bvd) {
    int idx = blockIdx.x * blockDim.x + threadIdx.x;
    const int total = EE * NTOT;
    if (idx < total) {
        int e = idx / NTOT;
        int n = idx % NTOT;
        float w;
        if (n < NQK) {
            int h = n >> 6, d = n & 63;
            w = Wq[(h * EE + e) * DD + d];
        } else if (n < 2 * NQK) {
            int nn = n - NQK;
            int h = nn >> 6, d = nn & 63;
            w = Wk[(h * EE + e) * DD + d];
        } else {
            int nn = n - 2 * NQK;
            int h = nn >> 4, r = nn & 15;
            w = Wvd[(h * EE + e) * RR + r];
        }
        g_Wall[idx] = f2tf(w);
    }
    if (idx < NTOT) {
        float bv;
        if (idx < NQK)          bv = bq[idx];
        else if (idx < 2 * NQK) bv = bk[idx - NQK];
        else                    bv = bvd[idx - 2 * NQK];
        g_ball[idx] = bv;
    }
}

// ---------------- fused QKV projection GEMM (tf32 tensor cores) ----------------
#define ASTR 20
#define BSTR 136
__global__ void __launch_bounds__(256) qkv_gemm_kernel(const float* __restrict__ X) {
    __shared__ uint32_t As[2][128 * ASTR];   // [m][k] tf32
    __shared__ uint32_t Bs[2][16 * BSTR];    // [k][n] tf32

    const int m0 = blockIdx.y * 128;
    const int n0 = blockIdx.x * 128;
    const int tid = threadIdx.x;
    const int lane = tid & 31;
    const int warp = tid >> 5;
    const int lg = lane >> 2;
    const int lr = lane & 3;
    const int wm = (warp >> 2) * 64;
    const int wn = (warp & 3) * 32;

    const int am = tid >> 1;
    const int ac = (tid & 1) * 8;
    const int bk = tid >> 4;
    const int bc = (tid & 15) * 8;

    float c[4][4][4];
#pragma unroll
    for (int i = 0; i < 4; ++i)
#pragma unroll
        for (int j = 0; j < 4; ++j)
#pragma unroll
            for (int e = 0; e < 4; ++e) c[i][j][e] = 0.f;

    float4 pa0, pa1;
    uint4 pb0, pb1;

    pa0 = *(const float4*)(X + (size_t)(m0 + am) * EE + ac);
    pa1 = *(const float4*)(X + (size_t)(m0 + am) * EE + ac + 4);
    pb0 = *(const uint4*)(g_Wall + (size_t)bk * NTOT + n0 + bc);
    pb1 = *(const uint4*)(g_Wall + (size_t)bk * NTOT + n0 + bc + 4);
    {
        uint4 u0 = make_uint4(f2tf(pa0.x), f2tf(pa0.y), f2tf(pa0.z), f2tf(pa0.w));
        uint4 u1 = make_uint4(f2tf(pa1.x), f2tf(pa1.y), f2tf(pa1.z), f2tf(pa1.w));
        *(uint4*)(&As[0][am * ASTR + ac])     = u0;
        *(uint4*)(&As[0][am * ASTR + ac + 4]) = u1;
        *(uint4*)(&Bs[0][bk * BSTR + bc])     = pb0;
        *(uint4*)(&Bs[0][bk * BSTR + bc + 4]) = pb1;
    }
    __syncthreads();

    const int NK = EE / 16;
    for (int kt = 0; kt < NK; ++kt) {
        const int cur = kt & 1;
        if (kt + 1 < NK) {
            int k0 = (kt + 1) * 16;
            pa0 = *(const float4*)(X + (size_t)(m0 + am) * EE + k0 + ac);
            pa1 = *(const float4*)(X + (size_t)(m0 + am) * EE + k0 + ac + 4);
            pb0 = *(const uint4*)(g_Wall + (size_t)(k0 + bk) * NTOT + n0 + bc);
            pb1 = *(const uint4*)(g_Wall + (size_t)(k0 + bk) * NTOT + n0 + bc + 4);
        }

#pragma unroll
        for (int kk = 0; kk < 2; ++kk) {
            uint32_t a[4][4];
#pragma unroll
            for (int mt = 0; mt < 4; ++mt) {
                int row = wm + mt * 16;
                a[mt][0] = As[cur][(row + lg) * ASTR + kk * 8 + lr];
                a[mt][1] = As[cur][(row + lg + 8) * ASTR + kk * 8 + lr];
                a[mt][2] = As[cur][(row + lg) * ASTR + kk * 8 + lr + 4];
                a[mt][3] = As[cur][(row + lg + 8) * ASTR + kk * 8 + lr + 4];
            }
            uint32_t b[4][2];
#pragma unroll
            for (int nt = 0; nt < 4; ++nt) {
                int col = wn + nt * 8 + lg;
                b[nt][0] = Bs[cur][(kk * 8 + lr) * BSTR + col];
                b[nt][1] = Bs[cur][(kk * 8 + lr + 4) * BSTR + col];
            }
#pragma unroll
            for (int mt = 0; mt < 4; ++mt)
#pragma unroll
                for (int nt = 0; nt < 4; ++nt)
                    mma_tf32(c[mt][nt], a[mt], b[nt][0], b[nt][1]);
        }

        if (kt + 1 < NK) {
            int nxt = cur ^ 1;
            uint4 u0 = make_uint4(f2tf(pa0.x), f2tf(pa0.y), f2tf(pa0.z), f2tf(pa0.w));
            uint4 u1 = make_uint4(f2tf(pa1.x), f2tf(pa1.y), f2tf(pa1.z), f2tf(pa1.w));
            *(uint4*)(&As[nxt][am * ASTR + ac])     = u0;
            *(uint4*)(&As[nxt][am * ASTR + ac + 4]) = u1;
            *(uint4*)(&Bs[nxt][bk * BSTR + bc])     = pb0;
            *(uint4*)(&Bs[nxt][bk * BSTR + bc + 4]) = pb1;
        }
        __syncthreads();
    }

#pragma unroll
    for (int mt = 0; mt < 4; ++mt) {
#pragma unroll
        for (int e2 = 0; e2 < 2; ++e2) {
            int m = m0 + wm + mt * 16 + lg + e2 * 8;
            int b = m >> 11;
            int s = m & 2047;
#pragma unroll
            for (int nt = 0; nt < 4; ++nt) {
                int n = n0 + wn + nt * 8 + 2 * lr;
                float2 bias = *(const float2*)(g_ball + n);
                float2 val;
                val.x = c[mt][nt][e2 * 2 + 0] + bias.x;
                val.y = c[mt][nt][e2 * 2 + 1] + bias.y;
                if (n < NQK) {
                    int h = n >> 6, d = n & 63;
                    *(float2*)(g_q + (((size_t)(b * HH + h)) * SS + s) * DD + d) = val;
                } else if (n < 2 * NQK) {
                    int nn = n - NQK;
                    int h = nn >> 6, d = nn & 63;
                    *(float2*)(g_k + (((size_t)(b * HH + h)) * SS + s) * DD + d) = val;
                } else {
                    int nn = n - 2 * NQK;
                    int h = nn >> 4, r = nn & 15;
                    *(float2*)(g_vd + (((size_t)(b * HH + h)) * SS + s) * RR + r) = val;
                }
            }
        }
    }
}

// ---------------- V up-projection ----------------
__global__ void vu_kernel(const float* __restrict__ Wvu, const float* __restrict__ bvu) {
    int g = blockIdx.x * 4 + threadIdx.y;
    int d = threadIdx.x;
    int h = (g >> 11) & 15;
    float acc = bvu[h * DD + d];
    const float* vdrow = g_vd + (size_t)g * RR;
    const float* w = Wvu + (size_t)h * RR * DD;
#pragma unroll
    for (int r = 0; r < RR; ++r) acc += vdrow[r] * w[r * DD + d];
    g_v[(size_t)g * DD + d] = acc;
}

// ---------------- flash attention: tf32, 128q x 64k tiles, 4 warps ----------------
// Warp m-tile = 32 rows (2 x m16). K stored column-pair-permuted, V transposed,
// so every B-fragment (2 regs) is one LDS.64 shared across both m-tiles.
#define SMS 68
__global__ void __launch_bounds__(128) attn_kernel(float* __restrict__ out) {
    extern __shared__ uint32_t sm[];
    uint32_t* Ks = sm;                // [64 keys][68]: permuted cols; also Q staging
    uint32_t* Vt = sm + 64 * SMS;     // [64 d][68 keys]: transposed V

    const int qt = blockIdx.x;        // 0..15
    const int bh = blockIdx.y;
    const int q0 = qt * 128;
    const float* qb = g_q + (size_t)bh * SS * DD;
    const float* kb = g_k + (size_t)bh * SS * DD;
    const float* vb = g_v + (size_t)bh * SS * DD;

    const int tid = threadIdx.x;
    const int lane = tid & 31;
    const int warp = tid >> 5;
    const int lg = lane >> 2;
    const int lr = lane & 3;

    // scale * log2(e): softmax done in base-2
    const float scale = 0.03125f * 1.4426950408889634f;

    // ---- stage Q (two 64-row halves through Ks), pull fragments ----
    uint32_t aq[2][8][4];
#pragma unroll
    for (int half = 0; half < 2; ++half) {
#pragma unroll
        for (int it = 0; it < 4; ++it) {
            int idx4 = tid + it * 128;   // 512 float4 slots (64 rows x 8... need 1024)
            // 64 rows x 16 float4 = 1024 slots -> 8 iters of 128
            (void)idx4;
        }
#pragma unroll
        for (int it = 0; it < 8; ++it) {
            int idx4 = tid + it * 128;
            int r = idx4 >> 4;
            int c4 = (idx4 & 15) * 4;
            float4 v4 = *(const float4*)(qb + (size_t)(q0 + half * 64 + r) * DD + c4);
            int dst = r * SMS + (c4 >> 3) * 8 + ((c4 & 4) ? 1 : 0);
            Ks[dst + 0] = f2tf(v4.x * scale);
            Ks[dst + 2] = f2tf(v4.y * scale);
            Ks[dst + 4] = f2tf(v4.z * scale);
            Ks[dst + 6] = f2tf(v4.w * scale);
        }
        __syncthreads();
        if ((warp >> 1) == half) {
#pragma unroll
            for (int mt = 0; mt < 2; ++mt) {
                int row = (warp & 1) * 32 + mt * 16 + lg;
#pragma unroll
                for (int kc = 0; kc < 8; ++kc) {
                    uint2 t0 = *(uint2*)(Ks + row * SMS + kc * 8 + 2 * lr);
                    uint2 t1 = *(uint2*)(Ks + (row + 8) * SMS + kc * 8 + 2 * lr);
                    aq[mt][kc][0] = t0.x;
                    aq[mt][kc][1] = t1.x;
                    aq[mt][kc][2] = t0.y;
                    aq[mt][kc][3] = t1.y;
                }
            }
        }
        __syncthreads();
    }

    float o[2][8][4];
    float mr[2][2], lr_[2][2];
#pragma unroll
    for (int mt = 0; mt < 2; ++mt) {
        mr[mt][0] = -1e30f; mr[mt][1] = -1e30f;
        lr_[mt][0] = 0.f;   lr_[mt][1] = 0.f;
#pragma unroll
        for (int j = 0; j < 8; ++j)
#pragma unroll
            for (int e = 0; e < 4; ++e) o[mt][j][e] = 0.f;
    }

    const int tstart = 2 * qt;
    for (int t = tstart; t < SS / 64; ++t) {
        __syncthreads();
        // stage K (permuted cols) and V (transposed)
#pragma unroll
        for (int it = 0; it < 8; ++it) {
            int idx4 = tid + it * 128;
            int r = idx4 >> 4;               // key local
            int c4 = (idx4 & 15) * 4;        // d base
            float4 kv = *(const float4*)(kb + (size_t)(t * 64 + r) * DD + c4);
            int dst = r * SMS + (c4 >> 3) * 8 + ((c4 & 4) ? 1 : 0);
            Ks[dst + 0] = f2tf(kv.x);
            Ks[dst + 2] = f2tf(kv.y);
            Ks[dst + 4] = f2tf(kv.z);
            Ks[dst + 6] = f2tf(kv.w);
            float4 vv = *(const float4*)(vb + (size_t)(t * 64 + r) * DD + c4);
            Vt[(c4 + 0) * SMS + r] = f2tf(vv.x);
            Vt[(c4 + 1) * SMS + r] = f2tf(vv.y);
            Vt[(c4 + 2) * SMS + r] = f2tf(vv.z);
            Vt[(c4 + 3) * SMS + r] = f2tf(vv.w);
        }
        __syncthreads();

        // ---- S = Q @ K^T ----
        float s[2][8][4];
#pragma unroll
        for (int mt = 0; mt < 2; ++mt)
#pragma unroll
            for (int j = 0; j < 8; ++j)
#pragma unroll
                for (int e = 0; e < 4; ++e) s[mt][j][e] = 0.f;

#pragma unroll
        for (int j = 0; j < 8; ++j) {
#pragma unroll
            for (int kc = 0; kc < 8; ++kc) {
                uint2 b = *(uint2*)(Ks + (j * 8 + lg) * SMS + kc * 8 + 2 * lr);
                mma_tf32(s[0][j], aq[0][kc], b.x, b.y);
                mma_tf32(s[1][j], aq[1][kc], b.x, b.y);
            }
        }

        // ---- reverse-causal mask on the first two tiles ----
        if (t < tstart + 2) {
#pragma unroll
            for (int mt = 0; mt < 2; ++mt) {
                int qr = q0 + warp * 32 + mt * 16 + lg;
#pragma unroll
                for (int j = 0; j < 8; ++j) {
                    int kg = t * 64 + j * 8 + lr * 2;
                    if (kg < qr)         s[mt][j][0] = -1e30f;
                    if (kg + 1 < qr)     s[mt][j][1] = -1e30f;
                    if (kg < qr + 8)     s[mt][j][2] = -1e30f;
                    if (kg + 1 < qr + 8) s[mt][j][3] = -1e30f;
                }
            }
        }

        // ---- online softmax (base-2) + P fragments ----
        uint32_t p[2][8][4];
#pragma unroll
        for (int mt = 0; mt < 2; ++mt) {
            float rm0 = -1e30f, rm1 = -1e30f;
#pragma unroll
            for (int j = 0; j < 8; ++j) {
                rm0 = fmaxf(rm0, fmaxf(s[mt][j][0], s[mt][j][1]));
                rm1 = fmaxf(rm1, fmaxf(s[mt][j][2], s[mt][j][3]));
            }
            rm0 = fmaxf(rm0, __shfl_xor_sync(0xffffffffu, rm0, 1));
            rm0 = fmaxf(rm0, __shfl_xor_sync(0xffffffffu, rm0, 2));
            rm1 = fmaxf(rm1, __shfl_xor_sync(0xffffffffu, rm1, 1));
            rm1 = fmaxf(rm1, __shfl_xor_sync(0xffffffffu, rm1, 2));

            float mn0 = fmaxf(mr[mt][0], rm0);
            float mn1 = fmaxf(mr[mt][1], rm1);
            float al0 = ex2(mr[mt][0] - mn0);
            float al1 = ex2(mr[mt][1] - mn1);
            mr[mt][0] = mn0; mr[mt][1] = mn1;

            float rs0 = 0.f, rs1 = 0.f;
#pragma unroll
            for (int j = 0; j < 8; ++j) {
                float p0 = ex2(s[mt][j][0] - mn0);
                float p1 = ex2(s[mt][j][1] - mn0);
                float p2 = ex2(s[mt][j][2] - mn1);
                float p3 = ex2(s[mt][j][3] - mn1);
                rs0 += p0 + p1;
                rs1 += p2 + p3;
                p[mt][j][0] = f2tf(p0); p[mt][j][1] = f2tf(p1);
                p[mt][j][2] = f2tf(p2); p[mt][j][3] = f2tf(p3);
            }
            rs0 += __shfl_xor_sync(0xffffffffu, rs0, 1);
            rs0 += __shfl_xor_sync(0xffffffffu, rs0, 2);
            rs1 += __shfl_xor_sync(0xffffffffu, rs1, 1);
            rs1 += __shfl_xor_sync(0xffffffffu, rs1, 2);
            lr_[mt][0] = lr_[mt][0] * al0 + rs0;
            lr_[mt][1] = lr_[mt][1] * al1 + rs1;

#pragma unroll
            for (int j = 0; j < 8; ++j) {
                o[mt][j][0] *= al0; o[mt][j][1] *= al0;
                o[mt][j][2] *= al1; o[mt][j][3] *= al1;
            }
        }

        // ---- O += P @ V ----
#pragma unroll
        for (int g = 0; g < 8; ++g) {
            uint32_t ap0[4], ap1[4];
            ap0[0] = p[0][g][0]; ap0[1] = p[0][g][2]; ap0[2] = p[0][g][1]; ap0[3] = p[0][g][3];
            ap1[0] = p[1][g][0]; ap1[1] = p[1][g][2]; ap1[2] = p[1][g][1]; ap1[3] = p[1][g][3];
#pragma unroll
            for (int j2 = 0; j2 < 8; ++j2) {
                uint2 b = *(uint2*)(Vt + (j2 * 8 + lg) * SMS + g * 8 + 2 * lr);
                mma_tf32(o[0][j2], ap0, b.x, b.y);
                mma_tf32(o[1][j2], ap1, b.x, b.y);
            }
        }
    }

    // ---- write normalized output ----
    int h = bh % HH, b = bh / HH;
#pragma unroll
    for (int mt = 0; mt < 2; ++mt) {
        int qr = q0 + warp * 32 + mt * 16 + lg;
        float inv0 = 1.f / lr_[mt][0];
        float inv1 = 1.f / lr_[mt][1];
#pragma unroll
        for (int j2 = 0; j2 < 8; ++j2) {
            int d = j2 * 8 + lr * 2;
            float2 v0 = make_float2(o[mt][j2][0] * inv0, o[mt][j2][1] * inv0);
            float2 v1 = make_float2(o[mt][j2][2] * inv1, o[mt][j2][3] * inv1);
            *(float2*)(out + (((size_t)(b * SS + qr)) * HH + h) * DD + d) = v0;
            *(float2*)(out + (((size_t)(b * SS + qr + 8)) * HH + h) * DD + d) = v1;
        }
    }
}

// ---------------- launcher ----------------
extern "C" void kernel_launch(void* const* d_in, const int* in_sizes, int n_in,
                              void* d_out, int out_size) {
    const float* x   = (const float*)d_in[0];
    const float* Wq  = (const float*)d_in[1];
    const float* bq  = (const float*)d_in[2];
    const float* Wk  = (const float*)d_in[3];
    const float* bk  = (const float*)d_in[4];
    const float* Wvd = (const float*)d_in[5];
    const float* bvd = (const float*)d_in[6];
    const float* Wvu = (const float*)d_in[7];
    const float* bvu = (const float*)d_in[8];
    float* out = (float*)d_out;

    {
        int total = EE * NTOT;
        pack_kernel<<<(total + 255) / 256, 256>>>(Wq, bq, Wk, bk, Wvd, bvd);
    }
    {
        dim3 grid(NTOT / 128, MROWS / 128);  // (18, 32)
        qkv_gemm_kernel<<<grid, 256>>>(x);
    }
    {
        dim3 block(64, 4);
        vu_kernel<<<(BH * SS) / 4, block>>>(Wvu, bvu);
    }
    {
        size_t smem = 2 * 64 * SMS * sizeof(float);  // 34816
        cudaFuncSetAttribute(attn_kernel, cudaFuncAttributeMaxDynamicSharedMemorySize, (int)smem);
        dim3 grid(SS / 128, BH);  // (16, 32)
        attn_kernel<<<grid, 128, smem>>>(out);
    }
}

// round 5
// speedup vs baseline: 1.0013x; 1.0013x over previous
#include <cuda_runtime.h>
#include <cuda_bf16.h>
#include <cstdint>

// Problem constants
#define BB 2
#define SS 2048
#define EE 1024
#define HH 16
#define DD 64
#define RR 16
#define BH (BB*HH)          // 32
#define NQK (HH*DD)         // 1024
#define NTOT (2*NQK + HH*RR) // 2304
#define MROWS (BB*SS)       // 4096

// ---------------- device scratch ----------------
__device__ uint32_t g_Wall[EE * NTOT];       // packed [E][2304], pre-converted tf32
__device__ float g_ball[NTOT];
__device__ float g_q[BH * SS * DD];          // (b,h,s,d)
__device__ float g_k[BH * SS * DD];
__device__ float g_vd[BH * SS * RR];
__device__ float g_v[BH * SS * DD];

// ---------------- tf32 helpers ----------------
__device__ __forceinline__ uint32_t f2tf(float f) {
    uint32_t r;
    asm("cvt.rna.tf32.f32 %0, %1;" : "=r"(r) : "f"(f));
    return r;
}

__device__ __forceinline__ float ex2(float x) {
    float r;
    asm("ex2.approx.f32 %0, %1;" : "=f"(r) : "f"(x));
    return r;
}

__device__ __forceinline__ void mma_tf32(float c[4], const uint32_t a[4], uint32_t b0, uint32_t b1) {
    asm volatile(
        "mma.sync.aligned.m16n8k8.row.col.f32.tf32.tf32.f32 "
        "{%0,%1,%2,%3}, {%4,%5,%6,%7}, {%8,%9}, {%0,%1,%2,%3};"
        : "+f"(c[0]), "+f"(c[1]), "+f"(c[2]), "+f"(c[3])
        : "r"(a[0]), "r"(a[1]), "r"(a[2]), "r"(a[3]), "r"(b0), "r"(b1));
}

// ---------------- pack weights (converts to tf32) ----------------
__global__ void pack_kernel(const float* __restrict__ Wq, const float* __restrict__ bq,
                            const float* __restrict__ Wk, const float* __restrict__ bk,
                            const float* __restrict__ Wvd, const float* __restrict__ bvd) {
    int idx = blockIdx.x * blockDim.x + threadIdx.x;
    const int total = EE * NTOT;
    if (idx < total) {
        int e = idx / NTOT;
        int n = idx % NTOT;
        float w;
        if (n < NQK) {
            int h = n >> 6, d = n & 63;
            w = Wq[(h * EE + e) * DD + d];
        } else if (n < 2 * NQK) {
            int nn = n - NQK;
            int h = nn >> 6, d = nn & 63;
            w = Wk[(h * EE + e) * DD + d];
        } else {
            int nn = n - 2 * NQK;
            int h = nn >> 4, r = nn & 15;
            w = Wvd[(h * EE + e) * RR + r];
        }
        g_Wall[idx] = f2tf(w);
    }
    if (idx < NTOT) {
        float bv;
        if (idx < NQK)          bv = bq[idx];
        else if (idx < 2 * NQK) bv = bk[idx - NQK];
        else                    bv = bvd[idx - 2 * NQK];
        g_ball[idx] = bv;
    }
}

// ---------------- fused QKV projection GEMM (tf32 tensor cores) ----------------
#define ASTR 20
#define BSTR 136
__global__ void __launch_bounds__(256) qkv_gemm_kernel(const float* __restrict__ X) {
    __shared__ uint32_t As[2][128 * ASTR];   // [m][k] tf32
    __shared__ uint32_t Bs[2][16 * BSTR];    // [k][n] tf32

    const int m0 = blockIdx.y * 128;
    const int n0 = blockIdx.x * 128;
    const int tid = threadIdx.x;
    const int lane = tid & 31;
    const int warp = tid >> 5;
    const int lg = lane >> 2;
    const int lr = lane & 3;
    const int wm = (warp >> 2) * 64;
    const int wn = (warp & 3) * 32;

    const int am = tid >> 1;
    const int ac = (tid & 1) * 8;
    const int bk = tid >> 4;
    const int bc = (tid & 15) * 8;

    float c[4][4][4];
#pragma unroll
    for (int i = 0; i < 4; ++i)
#pragma unroll
        for (int j = 0; j < 4; ++j)
#pragma unroll
            for (int e = 0; e < 4; ++e) c[i][j][e] = 0.f;

    float4 pa0, pa1;
    uint4 pb0, pb1;

    pa0 = *(const float4*)(X + (size_t)(m0 + am) * EE + ac);
    pa1 = *(const float4*)(X + (size_t)(m0 + am) * EE + ac + 4);
    pb0 = *(const uint4*)(g_Wall + (size_t)bk * NTOT + n0 + bc);
    pb1 = *(const uint4*)(g_Wall + (size_t)bk * NTOT + n0 + bc + 4);
    {
        uint4 u0 = make_uint4(f2tf(pa0.x), f2tf(pa0.y), f2tf(pa0.z), f2tf(pa0.w));
        uint4 u1 = make_uint4(f2tf(pa1.x), f2tf(pa1.y), f2tf(pa1.z), f2tf(pa1.w));
        *(uint4*)(&As[0][am * ASTR + ac])     = u0;
        *(uint4*)(&As[0][am * ASTR + ac + 4]) = u1;
        *(uint4*)(&Bs[0][bk * BSTR + bc])     = pb0;
        *(uint4*)(&Bs[0][bk * BSTR + bc + 4]) = pb1;
    }
    __syncthreads();

    const int NK = EE / 16;
    for (int kt = 0; kt < NK; ++kt) {
        const int cur = kt & 1;
        if (kt + 1 < NK) {
            int k0 = (kt + 1) * 16;
            pa0 = *(const float4*)(X + (size_t)(m0 + am) * EE + k0 + ac);
            pa1 = *(const float4*)(X + (size_t)(m0 + am) * EE + k0 + ac + 4);
            pb0 = *(const uint4*)(g_Wall + (size_t)(k0 + bk) * NTOT + n0 + bc);
            pb1 = *(const uint4*)(g_Wall + (size_t)(k0 + bk) * NTOT + n0 + bc + 4);
        }

#pragma unroll
        for (int kk = 0; kk < 2; ++kk) {
            uint32_t a[4][4];
#pragma unroll
            for (int mt = 0; mt < 4; ++mt) {
                int row = wm + mt * 16;
                a[mt][0] = As[cur][(row + lg) * ASTR + kk * 8 + lr];
                a[mt][1] = As[cur][(row + lg + 8) * ASTR + kk * 8 + lr];
                a[mt][2] = As[cur][(row + lg) * ASTR + kk * 8 + lr + 4];
                a[mt][3] = As[cur][(row + lg + 8) * ASTR + kk * 8 + lr + 4];
            }
            uint32_t b[4][2];
#pragma unroll
            for (int nt = 0; nt < 4; ++nt) {
                int col = wn + nt * 8 + lg;
                b[nt][0] = Bs[cur][(kk * 8 + lr) * BSTR + col];
                b[nt][1] = Bs[cur][(kk * 8 + lr + 4) * BSTR + col];
            }
#pragma unroll
            for (int mt = 0; mt < 4; ++mt)
#pragma unroll
                for (int nt = 0; nt < 4; ++nt)
                    mma_tf32(c[mt][nt], a[mt], b[nt][0], b[nt][1]);
        }

        if (kt + 1 < NK) {
            int nxt = cur ^ 1;
            uint4 u0 = make_uint4(f2tf(pa0.x), f2tf(pa0.y), f2tf(pa0.z), f2tf(pa0.w));
            uint4 u1 = make_uint4(f2tf(pa1.x), f2tf(pa1.y), f2tf(pa1.z), f2tf(pa1.w));
            *(uint4*)(&As[nxt][am * ASTR + ac])     = u0;
            *(uint4*)(&As[nxt][am * ASTR + ac + 4]) = u1;
            *(uint4*)(&Bs[nxt][bk * BSTR + bc])     = pb0;
            *(uint4*)(&Bs[nxt][bk * BSTR + bc + 4]) = pb1;
        }
        __syncthreads();
    }

#pragma unroll
    for (int mt = 0; mt < 4; ++mt) {
#pragma unroll
        for (int e2 = 0; e2 < 2; ++e2) {
            int m = m0 + wm + mt * 16 + lg + e2 * 8;
            int b = m >> 11;
            int s = m & 2047;
#pragma unroll
            for (int nt = 0; nt < 4; ++nt) {
                int n = n0 + wn + nt * 8 + 2 * lr;
                float2 bias = *(const float2*)(g_ball + n);
                float2 val;
                val.x = c[mt][nt][e2 * 2 + 0] + bias.x;
                val.y = c[mt][nt][e2 * 2 + 1] + bias.y;
                if (n < NQK) {
                    int h = n >> 6, d = n & 63;
                    *(float2*)(g_q + (((size_t)(b * HH + h)) * SS + s) * DD + d) = val;
                } else if (n < 2 * NQK) {
                    int nn = n - NQK;
                    int h = nn >> 6, d = nn & 63;
                    *(float2*)(g_k + (((size_t)(b * HH + h)) * SS + s) * DD + d) = val;
                } else {
                    int nn = n - 2 * NQK;
                    int h = nn >> 4, r = nn & 15;
                    *(float2*)(g_vd + (((size_t)(b * HH + h)) * SS + s) * RR + r) = val;
                }
            }
        }
    }
}

// ---------------- V up-projection ----------------
__global__ void vu_kernel(const float* __restrict__ Wvu, const float* __restrict__ bvu) {
    int g = blockIdx.x * 4 + threadIdx.y;
    int d = threadIdx.x;
    int h = (g >> 11) & 15;
    float acc = bvu[h * DD + d];
    const float* vdrow = g_vd + (size_t)g * RR;
    const float* w = Wvu + (size_t)h * RR * DD;
#pragma unroll
    for (int r = 0; r < RR; ++r) acc += vdrow[r] * w[r * DD + d];
    g_v[(size_t)g * DD + d] = acc;
}

// ---------------- flash attention: tf32, 64q x 64k, 4 warps ----------------
// K (and staged Q) use a column-pair-permuted layout so each S-loop B-fragment
// is a single LDS.64. V stays natural (conflict-free staging). Softmax base-2.
#define SMS 68
__global__ void __launch_bounds__(128) attn_kernel(float* __restrict__ out) {
    extern __shared__ uint32_t sm[];
    uint32_t* Ks = sm;                // [64 keys][68] permuted cols; also Q staging
    uint32_t* Vs = sm + 64 * SMS;     // [64 keys][68] natural [key][d]

    const int qt = blockIdx.x;
    const int bh = blockIdx.y;
    const int q0 = qt * 64;
    const float* qb = g_q + (size_t)bh * SS * DD;
    const float* kb = g_k + (size_t)bh * SS * DD;
    const float* vb = g_v + (size_t)bh * SS * DD;

    const int tid = threadIdx.x;
    const int lane = tid & 31;
    const int warp = tid >> 5;
    const int lg = lane >> 2;
    const int lr = lane & 3;

    // 1/sqrt(E) * log2(e): softmax in base-2
    const float scale = 0.03125f * 1.4426950408889634f;

    // ---- stage Q (scaled, tf32, permuted cols), pull fragments ----
#pragma unroll
    for (int it = 0; it < 8; ++it) {
        int idx4 = tid + it * 128;
        int r = idx4 >> 4;
        int c4 = (idx4 & 15) * 4;
        float4 v4 = *(const float4*)(qb + (size_t)(q0 + r) * DD + c4);
        int dst = r * SMS + (c4 >> 3) * 8 + ((c4 & 4) ? 1 : 0);
        Ks[dst + 0] = f2tf(v4.x * scale);
        Ks[dst + 2] = f2tf(v4.y * scale);
        Ks[dst + 4] = f2tf(v4.z * scale);
        Ks[dst + 6] = f2tf(v4.w * scale);
    }
    __syncthreads();

    uint32_t aq[8][4];
    {
        int row = warp * 16 + lg;
#pragma unroll
        for (int kc = 0; kc < 8; ++kc) {
            uint2 t0 = *(uint2*)(Ks + row * SMS + kc * 8 + 2 * lr);
            uint2 t1 = *(uint2*)(Ks + (row + 8) * SMS + kc * 8 + 2 * lr);
            aq[kc][0] = t0.x;
            aq[kc][1] = t1.x;
            aq[kc][2] = t0.y;
            aq[kc][3] = t1.y;
        }
    }

    float o[8][4];
    float m0r = -1e30f, m1r = -1e30f, l0r = 0.f, l1r = 0.f;
#pragma unroll
    for (int j = 0; j < 8; ++j)
#pragma unroll
        for (int e = 0; e < 4; ++e) o[j][e] = 0.f;

    for (int t = qt; t < SS / 64; ++t) {
        __syncthreads();
        // stage K (permuted) and V (natural)
#pragma unroll
        for (int it = 0; it < 8; ++it) {
            int idx4 = tid + it * 128;
            int r = idx4 >> 4;
            int c4 = (idx4 & 15) * 4;
            float4 kv = *(const float4*)(kb + (size_t)(t * 64 + r) * DD + c4);
            int dst = r * SMS + (c4 >> 3) * 8 + ((c4 & 4) ? 1 : 0);
            Ks[dst + 0] = f2tf(kv.x);
            Ks[dst + 2] = f2tf(kv.y);
            Ks[dst + 4] = f2tf(kv.z);
            Ks[dst + 6] = f2tf(kv.w);
            float4 vv = *(const float4*)(vb + (size_t)(t * 64 + r) * DD + c4);
            uint4 uv;
            uv.x = f2tf(vv.x); uv.y = f2tf(vv.y); uv.z = f2tf(vv.z); uv.w = f2tf(vv.w);
            *(uint4*)(Vs + r * SMS + c4) = uv;
        }
        __syncthreads();

        // ---- S = Q @ K^T ----
        float s[8][4];
#pragma unroll
        for (int j = 0; j < 8; ++j)
#pragma unroll
            for (int e = 0; e < 4; ++e) s[j][e] = 0.f;

#pragma unroll
        for (int j = 0; j < 8; ++j) {
#pragma unroll
            for (int kc = 0; kc < 8; ++kc) {
                uint2 b = *(uint2*)(Ks + (j * 8 + lg) * SMS + kc * 8 + 2 * lr);
                mma_tf32(s[j], aq[kc], b.x, b.y);
            }
        }

        // ---- reverse-causal mask (diagonal tile only) ----
        if (t == qt) {
            int qr0 = q0 + warp * 16 + lg;
#pragma unroll
            for (int j = 0; j < 8; ++j) {
                int kg = t * 64 + j * 8 + lr * 2;
                if (kg < qr0)          s[j][0] = -1e30f;
                if (kg + 1 < qr0)      s[j][1] = -1e30f;
                if (kg < qr0 + 8)      s[j][2] = -1e30f;
                if (kg + 1 < qr0 + 8)  s[j][3] = -1e30f;
            }
        }

        // ---- online softmax (base-2); P written in place over s ----
        float rm0 = -1e30f, rm1 = -1e30f;
#pragma unroll
        for (int j = 0; j < 8; ++j) {
            rm0 = fmaxf(rm0, fmaxf(s[j][0], s[j][1]));
            rm1 = fmaxf(rm1, fmaxf(s[j][2], s[j][3]));
        }
        rm0 = fmaxf(rm0, __shfl_xor_sync(0xffffffffu, rm0, 1));
        rm0 = fmaxf(rm0, __shfl_xor_sync(0xffffffffu, rm0, 2));
        rm1 = fmaxf(rm1, __shfl_xor_sync(0xffffffffu, rm1, 1));
        rm1 = fmaxf(rm1, __shfl_xor_sync(0xffffffffu, rm1, 2));

        float mn0 = fmaxf(m0r, rm0);
        float mn1 = fmaxf(m1r, rm1);
        float al0 = ex2(m0r - mn0);
        float al1 = ex2(m1r - mn1);
        m0r = mn0; m1r = mn1;

        float rs0 = 0.f, rs1 = 0.f;
#pragma unroll
        for (int j = 0; j < 8; ++j) {
            float p0 = ex2(s[j][0] - mn0);
            float p1 = ex2(s[j][1] - mn0);
            float p2 = ex2(s[j][2] - mn1);
            float p3 = ex2(s[j][3] - mn1);
            rs0 += p0 + p1;
            rs1 += p2 + p3;
            s[j][0] = __uint_as_float(f2tf(p0));
            s[j][1] = __uint_as_float(f2tf(p1));
            s[j][2] = __uint_as_float(f2tf(p2));
            s[j][3] = __uint_as_float(f2tf(p3));
        }
        rs0 += __shfl_xor_sync(0xffffffffu, rs0, 1);
        rs0 += __shfl_xor_sync(0xffffffffu, rs0, 2);
        rs1 += __shfl_xor_sync(0xffffffffu, rs1, 1);
        rs1 += __shfl_xor_sync(0xffffffffu, rs1, 2);
        l0r = l0r * al0 + rs0;
        l1r = l1r * al1 + rs1;

#pragma unroll
        for (int j = 0; j < 8; ++j) {
            o[j][0] *= al0; o[j][1] *= al0;
            o[j][2] *= al1; o[j][3] *= al1;
        }

        // ---- O += P @ V  (P from C-fragments via V row permutation) ----
#pragma unroll
        for (int g = 0; g < 8; ++g) {
            uint32_t ap[4];
            ap[0] = __float_as_uint(s[g][0]);
            ap[1] = __float_as_uint(s[g][2]);
            ap[2] = __float_as_uint(s[g][1]);
            ap[3] = __float_as_uint(s[g][3]);
#pragma unroll
            for (int j2 = 0; j2 < 8; ++j2) {
                uint32_t b0 = Vs[(g * 8 + 2 * lr) * SMS + j2 * 8 + lg];
                uint32_t b1 = Vs[(g * 8 + 2 * lr + 1) * SMS + j2 * 8 + lg];
                mma_tf32(o[j2], ap, b0, b1);
            }
        }
    }

    // ---- write normalized output ----
    int h = bh % HH, b = bh / HH;
    float inv0 = 1.f / l0r;
    float inv1 = 1.f / l1r;
    int qr0 = q0 + warp * 16 + lg;
#pragma unroll
    for (int j2 = 0; j2 < 8; ++j2) {
        int d = j2 * 8 + lr * 2;
        float2 v0 = make_float2(o[j2][0] * inv0, o[j2][1] * inv0);
        float2 v1 = make_float2(o[j2][2] * inv1, o[j2][3] * inv1);
        *(float2*)(out + (((size_t)(b * SS + qr0)) * HH + h) * DD + d) = v0;
        *(float2*)(out + (((size_t)(b * SS + qr0 + 8)) * HH + h) * DD + d) = v1;
    }
}

// ---------------- launcher ----------------
extern "C" void kernel_launch(void* const* d_in, const int* in_sizes, int n_in,
                              void* d_out, int out_size) {
    const float* x   = (const float*)d_in[0];
    const float* Wq  = (const float*)d_in[1];
    const float* bq  = (const float*)d_in[2];
    const float* Wk  = (const float*)d_in[3];
    const float* bk  = (const float*)d_in[4];
    const float* Wvd = (const float*)d_in[5];
    const float* bvd = (const float*)d_in[6];
    const float* Wvu = (const float*)d_in[7];
    const float* bvu = (const float*)d_in[8];
    float* out = (float*)d_out;

    {
        int total = EE * NTOT;
        pack_kernel<<<(total + 255) / 256, 256>>>(Wq, bq, Wk, bk, Wvd, bvd);
    }
    {
        dim3 grid(NTOT / 128, MROWS / 128);  // (18, 32)
        qkv_gemm_kernel<<<grid, 256>>>(x);
    }
    {
        dim3 block(64, 4);
        vu_kernel<<<(BH * SS) / 4, block>>>(Wvu, bvu);
    }
    {
        size_t smem = 2 * 64 * SMS * sizeof(float);  // 34816
        cudaFuncSetAttribute(attn_kernel, cudaFuncAttributeMaxDynamicSharedMemorySize, (int)smem);
        dim3 grid(SS / 64, BH);  // (32, 32)
        attn_kernel<<<grid, 128, smem>>>(out);
    }
}

// round 6
// speedup vs baseline: 1.0961x; 1.0947x over previous
#include <cuda_runtime.h>
#include <cuda_bf16.h>
#include <cstdint>

// Problem constants
#define BB 2
#define SS 2048
#define EE 1024
#define HH 16
#define DD 64
#define RR 16
#define BH (BB*HH)          // 32
#define NQK (HH*DD)         // 1024
#define NTOT (2*NQK + HH*RR) // 2304
#define MROWS (BB*SS)       // 4096

// ---------------- device scratch ----------------
__device__ uint32_t g_Wall[EE * NTOT];       // packed [E][2304], pre-converted tf32
__device__ float g_ball[NTOT];
__device__ float g_q[BH * SS * DD];          // (b,h,s,d)
__device__ float g_k[BH * SS * DD];
__device__ float g_vd[BH * SS * RR];
__device__ float g_v[BH * SS * DD];

// ---------------- tf32 helpers ----------------
__device__ __forceinline__ uint32_t f2tf(float f) {
    uint32_t r;
    asm("cvt.rna.tf32.f32 %0, %1;" : "=r"(r) : "f"(f));
    return r;
}

__device__ __forceinline__ float ex2(float x) {
    float r;
    asm("ex2.approx.f32 %0, %1;" : "=f"(r) : "f"(x));
    return r;
}

__device__ __forceinline__ void mma_tf32(float c[4], const uint32_t a[4], uint32_t b0, uint32_t b1) {
    asm volatile(
        "mma.sync.aligned.m16n8k8.row.col.f32.tf32.tf32.f32 "
        "{%0,%1,%2,%3}, {%4,%5,%6,%7}, {%8,%9}, {%0,%1,%2,%3};"
        : "+f"(c[0]), "+f"(c[1]), "+f"(c[2]), "+f"(c[3])
        : "r"(a[0]), "r"(a[1]), "r"(a[2]), "r"(a[3]), "r"(b0), "r"(b1));
}

// ---------------- pack weights (converts to tf32) ----------------
__global__ void pack_kernel(const float* __restrict__ Wq, const float* __restrict__ bq,
                            const float* __restrict__ Wk, const float* __restrict__ bk,
                            const float* __restrict__ Wvd, const float* __restrict__ bvd) {
    int idx = blockIdx.x * blockDim.x + threadIdx.x;
    const int total = EE * NTOT;
    if (idx < total) {
        int e = idx / NTOT;
        int n = idx % NTOT;
        float w;
        if (n < NQK) {
            int h = n >> 6, d = n & 63;
            w = Wq[(h * EE + e) * DD + d];
        } else if (n < 2 * NQK) {
            int nn = n - NQK;
            int h = nn >> 6, d = nn & 63;
            w = Wk[(h * EE + e) * DD + d];
        } else {
            int nn = n - 2 * NQK;
            int h = nn >> 4, r = nn & 15;
            w = Wvd[(h * EE + e) * RR + r];
        }
        g_Wall[idx] = f2tf(w);
    }
    if (idx < NTOT) {
        float bv;
        if (idx < NQK)          bv = bq[idx];
        else if (idx < 2 * NQK) bv = bk[idx - NQK];
        else                    bv = bvd[idx - 2 * NQK];
        g_ball[idx] = bv;
    }
}

// ---------------- fused QKV projection GEMM (tf32 tensor cores) ----------------
#define ASTR 20
#define BSTR 136
__global__ void __launch_bounds__(256) qkv_gemm_kernel(const float* __restrict__ X) {
    __shared__ uint32_t As[2][128 * ASTR];   // [m][k] tf32
    __shared__ uint32_t Bs[2][16 * BSTR];    // [k][n] tf32

    const int m0 = blockIdx.y * 128;
    const int n0 = blockIdx.x * 128;
    const int tid = threadIdx.x;
    const int lane = tid & 31;
    const int warp = tid >> 5;
    const int lg = lane >> 2;
    const int lr = lane & 3;
    const int wm = (warp >> 2) * 64;
    const int wn = (warp & 3) * 32;

    const int am = tid >> 1;
    const int ac = (tid & 1) * 8;
    const int bk = tid >> 4;
    const int bc = (tid & 15) * 8;

    float c[4][4][4];
#pragma unroll
    for (int i = 0; i < 4; ++i)
#pragma unroll
        for (int j = 0; j < 4; ++j)
#pragma unroll
            for (int e = 0; e < 4; ++e) c[i][j][e] = 0.f;

    float4 pa0, pa1;
    uint4 pb0, pb1;

    pa0 = *(const float4*)(X + (size_t)(m0 + am) * EE + ac);
    pa1 = *(const float4*)(X + (size_t)(m0 + am) * EE + ac + 4);
    pb0 = *(const uint4*)(g_Wall + (size_t)bk * NTOT + n0 + bc);
    pb1 = *(const uint4*)(g_Wall + (size_t)bk * NTOT + n0 + bc + 4);
    {
        uint4 u0 = make_uint4(f2tf(pa0.x), f2tf(pa0.y), f2tf(pa0.z), f2tf(pa0.w));
        uint4 u1 = make_uint4(f2tf(pa1.x), f2tf(pa1.y), f2tf(pa1.z), f2tf(pa1.w));
        *(uint4*)(&As[0][am * ASTR + ac])     = u0;
        *(uint4*)(&As[0][am * ASTR + ac + 4]) = u1;
        *(uint4*)(&Bs[0][bk * BSTR + bc])     = pb0;
        *(uint4*)(&Bs[0][bk * BSTR + bc + 4]) = pb1;
    }
    __syncthreads();

    const int NK = EE / 16;
    for (int kt = 0; kt < NK; ++kt) {
        const int cur = kt & 1;
        if (kt + 1 < NK) {
            int k0 = (kt + 1) * 16;
            pa0 = *(const float4*)(X + (size_t)(m0 + am) * EE + k0 + ac);
            pa1 = *(const float4*)(X + (size_t)(m0 + am) * EE + k0 + ac + 4);
            pb0 = *(const uint4*)(g_Wall + (size_t)(k0 + bk) * NTOT + n0 + bc);
            pb1 = *(const uint4*)(g_Wall + (size_t)(k0 + bk) * NTOT + n0 + bc + 4);
        }

#pragma unroll
        for (int kk = 0; kk < 2; ++kk) {
            uint32_t a[4][4];
#pragma unroll
            for (int mt = 0; mt < 4; ++mt) {
                int row = wm + mt * 16;
                a[mt][0] = As[cur][(row + lg) * ASTR + kk * 8 + lr];
                a[mt][1] = As[cur][(row + lg + 8) * ASTR + kk * 8 + lr];
                a[mt][2] = As[cur][(row + lg) * ASTR + kk * 8 + lr + 4];
                a[mt][3] = As[cur][(row + lg + 8) * ASTR + kk * 8 + lr + 4];
            }
            uint32_t b[4][2];
#pragma unroll
            for (int nt = 0; nt < 4; ++nt) {
                int col = wn + nt * 8 + lg;
                b[nt][0] = Bs[cur][(kk * 8 + lr) * BSTR + col];
                b[nt][1] = Bs[cur][(kk * 8 + lr + 4) * BSTR + col];
            }
#pragma unroll
            for (int mt = 0; mt < 4; ++mt)
#pragma unroll
                for (int nt = 0; nt < 4; ++nt)
                    mma_tf32(c[mt][nt], a[mt], b[nt][0], b[nt][1]);
        }

        if (kt + 1 < NK) {
            int nxt = cur ^ 1;
            uint4 u0 = make_uint4(f2tf(pa0.x), f2tf(pa0.y), f2tf(pa0.z), f2tf(pa0.w));
            uint4 u1 = make_uint4(f2tf(pa1.x), f2tf(pa1.y), f2tf(pa1.z), f2tf(pa1.w));
            *(uint4*)(&As[nxt][am * ASTR + ac])     = u0;
            *(uint4*)(&As[nxt][am * ASTR + ac + 4]) = u1;
            *(uint4*)(&Bs[nxt][bk * BSTR + bc])     = pb0;
            *(uint4*)(&Bs[nxt][bk * BSTR + bc + 4]) = pb1;
        }
        __syncthreads();
    }

#pragma unroll
    for (int mt = 0; mt < 4; ++mt) {
#pragma unroll
        for (int e2 = 0; e2 < 2; ++e2) {
            int m = m0 + wm + mt * 16 + lg + e2 * 8;
            int b = m >> 11;
            int s = m & 2047;
#pragma unroll
            for (int nt = 0; nt < 4; ++nt) {
                int n = n0 + wn + nt * 8 + 2 * lr;
                float2 bias = *(const float2*)(g_ball + n);
                float2 val;
                val.x = c[mt][nt][e2 * 2 + 0] + bias.x;
                val.y = c[mt][nt][e2 * 2 + 1] + bias.y;
                if (n < NQK) {
                    int h = n >> 6, d = n & 63;
                    *(float2*)(g_q + (((size_t)(b * HH + h)) * SS + s) * DD + d) = val;
                } else if (n < 2 * NQK) {
                    int nn = n - NQK;
                    int h = nn >> 6, d = nn & 63;
                    *(float2*)(g_k + (((size_t)(b * HH + h)) * SS + s) * DD + d) = val;
                } else {
                    int nn = n - 2 * NQK;
                    int h = nn >> 4, r = nn & 15;
                    *(float2*)(g_vd + (((size_t)(b * HH + h)) * SS + s) * RR + r) = val;
                }
            }
        }
    }
}

// ---------------- V up-projection ----------------
__global__ void vu_kernel(const float* __restrict__ Wvu, const float* __restrict__ bvu) {
    int g = blockIdx.x * 4 + threadIdx.y;
    int d = threadIdx.x;
    int h = (g >> 11) & 15;
    float acc = bvu[h * DD + d];
    const float* vdrow = g_vd + (size_t)g * RR;
    const float* w = Wvu + (size_t)h * RR * DD;
#pragma unroll
    for (int r = 0; r < RR; ++r) acc += vdrow[r] * w[r * DD + d];
    g_v[(size_t)g * DD + d] = acc;
}

// ---------------- flash attention: tf32 tensor-core (R3 structure + ex2) ----------
#define SMS 68
__global__ void __launch_bounds__(128) attn_kernel(float* __restrict__ out) {
    extern __shared__ uint32_t sm[];
    uint32_t* Ks = sm;                // [64][68]
    uint32_t* Vs = sm + 64 * SMS;     // [64][68]

    const int qt = blockIdx.x;
    const int bh = blockIdx.y;
    const int q0 = qt * 64;
    const float* qb = g_q + (size_t)bh * SS * DD;
    const float* kb = g_k + (size_t)bh * SS * DD;
    const float* vb = g_v + (size_t)bh * SS * DD;

    const int tid = threadIdx.x;
    const int lane = tid & 31;
    const int warp = tid >> 5;
    const int lg = lane >> 2;
    const int lr = lane & 3;

    // 1/sqrt(E) * log2(e): softmax in base-2
    const float scale = 0.03125f * 1.4426950408889634f;

#pragma unroll
    for (int it = 0; it < 8; ++it) {
        int idx4 = tid + it * 128;
        int r = idx4 >> 4;
        int c4 = (idx4 & 15) * 4;
        float4 v4 = *(const float4*)(qb + (size_t)(q0 + r) * DD + c4);
        uint4 u;
        u.x = f2tf(v4.x * scale); u.y = f2tf(v4.y * scale);
        u.z = f2tf(v4.z * scale); u.w = f2tf(v4.w * scale);
        *(uint4*)(Ks + r * SMS + c4) = u;
    }
    __syncthreads();

    uint32_t aq[8][4];
    {
        int row = warp * 16 + lg;
#pragma unroll
        for (int kc = 0; kc < 8; ++kc) {
            aq[kc][0] = Ks[row * SMS + kc * 8 + lr];
            aq[kc][1] = Ks[(row + 8) * SMS + kc * 8 + lr];
            aq[kc][2] = Ks[row * SMS + kc * 8 + lr + 4];
            aq[kc][3] = Ks[(row + 8) * SMS + kc * 8 + lr + 4];
        }
    }

    float o[8][4];
    float m0r = -1e30f, m1r = -1e30f, l0r = 0.f, l1r = 0.f;
#pragma unroll
    for (int j = 0; j < 8; ++j)
#pragma unroll
        for (int e = 0; e < 4; ++e) o[j][e] = 0.f;

    for (int t = qt; t < SS / 64; ++t) {
        __syncthreads();
#pragma unroll
        for (int it = 0; it < 8; ++it) {
            int idx4 = tid + it * 128;
            int r = idx4 >> 4;
            int c4 = (idx4 & 15) * 4;
            float4 kv = *(const float4*)(kb + (size_t)(t * 64 + r) * DD + c4);
            uint4 uk;
            uk.x = f2tf(kv.x); uk.y = f2tf(kv.y); uk.z = f2tf(kv.z); uk.w = f2tf(kv.w);
            *(uint4*)(Ks + r * SMS + c4) = uk;
            float4 vv = *(const float4*)(vb + (size_t)(t * 64 + r) * DD + c4);
            uint4 uv;
            uv.x = f2tf(vv.x); uv.y = f2tf(vv.y); uv.z = f2tf(vv.z); uv.w = f2tf(vv.w);
            *(uint4*)(Vs + r * SMS + c4) = uv;
        }
        __syncthreads();

        float s[8][4];
#pragma unroll
        for (int j = 0; j < 8; ++j)
#pragma unroll
            for (int e = 0; e < 4; ++e) s[j][e] = 0.f;

#pragma unroll
        for (int j = 0; j < 8; ++j) {
#pragma unroll
            for (int kc = 0; kc < 8; ++kc) {
                uint32_t b0 = Ks[(j * 8 + lg) * SMS + kc * 8 + lr];
                uint32_t b1 = Ks[(j * 8 + lg) * SMS + kc * 8 + lr + 4];
                mma_tf32(s[j], aq[kc], b0, b1);
            }
        }

        if (t == qt) {
            int qr0 = q0 + warp * 16 + lg;
#pragma unroll
            for (int j = 0; j < 8; ++j) {
                int kg = t * 64 + j * 8 + lr * 2;
                if (kg < qr0)          s[j][0] = -1e30f;
                if (kg + 1 < qr0)      s[j][1] = -1e30f;
                if (kg < qr0 + 8)      s[j][2] = -1e30f;
                if (kg + 1 < qr0 + 8)  s[j][3] = -1e30f;
            }
        }

        float rm0 = -1e30f, rm1 = -1e30f;
#pragma unroll
        for (int j = 0; j < 8; ++j) {
            rm0 = fmaxf(rm0, fmaxf(s[j][0], s[j][1]));
            rm1 = fmaxf(rm1, fmaxf(s[j][2], s[j][3]));
        }
        rm0 = fmaxf(rm0, __shfl_xor_sync(0xffffffffu, rm0, 1));
        rm0 = fmaxf(rm0, __shfl_xor_sync(0xffffffffu, rm0, 2));
        rm1 = fmaxf(rm1, __shfl_xor_sync(0xffffffffu, rm1, 1));
        rm1 = fmaxf(rm1, __shfl_xor_sync(0xffffffffu, rm1, 2));

        float mn0 = fmaxf(m0r, rm0);
        float mn1 = fmaxf(m1r, rm1);
        float al0 = ex2(m0r - mn0);
        float al1 = ex2(m1r - mn1);
        m0r = mn0; m1r = mn1;

        float rs0 = 0.f, rs1 = 0.f;
        uint32_t p[8][4];
#pragma unroll
        for (int j = 0; j < 8; ++j) {
            float p0 = ex2(s[j][0] - mn0);
            float p1 = ex2(s[j][1] - mn0);
            float p2 = ex2(s[j][2] - mn1);
            float p3 = ex2(s[j][3] - mn1);
            rs0 += p0 + p1;
            rs1 += p2 + p3;
            p[j][0] = f2tf(p0); p[j][1] = f2tf(p1);
            p[j][2] = f2tf(p2); p[j][3] = f2tf(p3);
        }
        rs0 += __shfl_xor_sync(0xffffffffu, rs0, 1);
        rs0 += __shfl_xor_sync(0xffffffffu, rs0, 2);
        rs1 += __shfl_xor_sync(0xffffffffu, rs1, 1);
        rs1 += __shfl_xor_sync(0xffffffffu, rs1, 2);
        l0r = l0r * al0 + rs0;
        l1r = l1r * al1 + rs1;

#pragma unroll
        for (int j = 0; j < 8; ++j) {
            o[j][0] *= al0; o[j][1] *= al0;
            o[j][2] *= al1; o[j][3] *= al1;
        }

#pragma unroll
        for (int g = 0; g < 8; ++g) {
            uint32_t ap[4];
            ap[0] = p[g][0]; ap[1] = p[g][2]; ap[2] = p[g][1]; ap[3] = p[g][3];
#pragma unroll
            for (int j2 = 0; j2 < 8; ++j2) {
                uint32_t b0 = Vs[(g * 8 + 2 * lr) * SMS + j2 * 8 + lg];
                uint32_t b1 = Vs[(g * 8 + 2 * lr + 1) * SMS + j2 * 8 + lg];
                mma_tf32(o[j2], ap, b0, b1);
            }
        }
    }

    int h = bh % HH, b = bh / HH;
    float inv0 = 1.f / l0r;
    float inv1 = 1.f / l1r;
    int qr0 = q0 + warp * 16 + lg;
#pragma unroll
    for (int j2 = 0; j2 < 8; ++j2) {
        int d = j2 * 8 + lr * 2;
        float2 v0 = make_float2(o[j2][0] * inv0, o[j2][1] * inv0);
        float2 v1 = make_float2(o[j2][2] * inv1, o[j2][3] * inv1);
        *(float2*)(out + (((size_t)(b * SS + qr0)) * HH + h) * DD + d) = v0;
        *(float2*)(out + (((size_t)(b * SS + qr0 + 8)) * HH + h) * DD + d) = v1;
    }
}

// ---------------- launcher ----------------
extern "C" void kernel_launch(void* const* d_in, const int* in_sizes, int n_in,
                              void* d_out, int out_size) {
    const float* x   = (const float*)d_in[0];
    const float* Wq  = (const float*)d_in[1];
    const float* bq  = (const float*)d_in[2];
    const float* Wk  = (const float*)d_in[3];
    const float* bk  = (const float*)d_in[4];
    const float* Wvd = (const float*)d_in[5];
    const float* bvd = (const float*)d_in[6];
    const float* Wvu = (const float*)d_in[7];
    const float* bvu = (const float*)d_in[8];
    float* out = (float*)d_out;

    {
        int total = EE * NTOT;
        pack_kernel<<<(total + 255) / 256, 256>>>(Wq, bq, Wk, bk, Wvd, bvd);
    }
    {
        dim3 grid(NTOT / 128, MROWS / 128);  // (18, 32)
        qkv_gemm_kernel<<<grid, 256>>>(x);
    }
    {
        dim3 block(64, 4);
        vu_kernel<<<(BH * SS) / 4, block>>>(Wvu, bvu);
    }
    {
        size_t smem = 2 * 64 * SMS * sizeof(float);
        cudaFuncSetAttribute(attn_kernel, cudaFuncAttributeMaxDynamicSharedMemorySize, (int)smem);
        dim3 grid(SS / 64, BH);  // (32, 32)
        attn_kernel<<<grid, 128, smem>>>(out);
    }
}

// round 7
// speedup vs baseline: 1.2713x; 1.1598x over previous
#include <cuda_runtime.h>
#include <cuda_fp16.h>
#include <cstdint>

// Problem constants
#define BB 2
#define SS 2048
#define EE 1024
#define HH 16
#define DD 64
#define RR 16
#define BH (BB*HH)          // 32
#define NQK (HH*DD)         // 1024
#define NTOT (2*NQK + HH*RR) // 2304
#define MROWS (BB*SS)       // 4096

// 1/sqrt(E) * log2(e)
#define QSCALE (0.03125f * 1.4426950408889634f)

// ---------------- device scratch ----------------
__device__ __half g_Wh[EE * NTOT];           // packed weights [k][n] fp16
__device__ __half g_Xh[MROWS * EE];          // x in fp16
__device__ float  g_ball[NTOT];
__device__ __half g_qh[BH * SS * DD];        // (b,h,s,d) pre-scaled fp16
__device__ __half g_kh[BH * SS * DD];
__device__ float  g_vd[BH * SS * RR];
__device__ __half g_vh[BH * SS * DD];

// ---------------- helpers ----------------
__device__ __forceinline__ float ex2(float x) {
    float r;
    asm("ex2.approx.f32 %0, %1;" : "=f"(r) : "f"(x));
    return r;
}

// pack two floats to fp16x2: lo bits = lo, hi bits = hi
__device__ __forceinline__ uint32_t f16x2(float hi, float lo) {
    uint32_t r;
    asm("cvt.rn.f16x2.f32 %0, %1, %2;" : "=r"(r) : "f"(hi), "f"(lo));
    return r;
}

__device__ __forceinline__ uint32_t prmt(uint32_t a, uint32_t b, uint32_t sel) {
    uint32_t r;
    asm("prmt.b32 %0, %1, %2, %3;" : "=r"(r) : "r"(a), "r"(b), "r"(sel));
    return r;
}

__device__ __forceinline__ void mma_f16(float c[4], const uint32_t a[4], uint32_t b0, uint32_t b1) {
    asm volatile(
        "mma.sync.aligned.m16n8k16.row.col.f32.f16.f16.f32 "
        "{%0,%1,%2,%3}, {%4,%5,%6,%7}, {%8,%9}, {%0,%1,%2,%3};"
        : "+f"(c[0]), "+f"(c[1]), "+f"(c[2]), "+f"(c[3])
        : "r"(a[0]), "r"(a[1]), "r"(a[2]), "r"(a[3]), "r"(b0), "r"(b1));
}

__device__ __forceinline__ void ldsm4(uint32_t& r0, uint32_t& r1, uint32_t& r2, uint32_t& r3, uint32_t addr) {
    asm volatile("ldmatrix.sync.aligned.m8n8.x4.shared.b16 {%0,%1,%2,%3}, [%4];"
                 : "=r"(r0), "=r"(r1), "=r"(r2), "=r"(r3) : "r"(addr));
}

__device__ __forceinline__ void ldsm4t(uint32_t& r0, uint32_t& r1, uint32_t& r2, uint32_t& r3, uint32_t addr) {
    asm volatile("ldmatrix.sync.aligned.m8n8.x4.trans.shared.b16 {%0,%1,%2,%3}, [%4];"
                 : "=r"(r0), "=r"(r1), "=r"(r2), "=r"(r3) : "r"(addr));
}

// ---------------- X -> fp16 ----------------
__global__ void xh_kernel(const float* __restrict__ X) {
    int g = blockIdx.x * blockDim.x + threadIdx.x;   // one per 8 elems
    int idx = g * 8;
    float4 f0 = *(const float4*)(X + idx);
    float4 f1 = *(const float4*)(X + idx + 4);
    uint4 u;
    u.x = f16x2(f0.y, f0.x);
    u.y = f16x2(f0.w, f0.z);
    u.z = f16x2(f1.y, f1.x);
    u.w = f16x2(f1.w, f1.z);
    *(uint4*)(g_Xh + idx) = u;
}

// ---------------- pack weights -> fp16 [k][n] ----------------
__global__ void pack_kernel(const float* __restrict__ Wq, const float* __restrict__ bq,
                            const float* __restrict__ Wk, const float* __restrict__ bk,
                            const float* __restrict__ Wvd, const float* __restrict__ bvd) {
    int idx = blockIdx.x * blockDim.x + threadIdx.x;
    const int total = EE * NTOT;
    if (idx < total) {
        int e = idx / NTOT;
        int n = idx % NTOT;
        float w;
        if (n < NQK) {
            int h = n >> 6, d = n & 63;
            w = Wq[(h * EE + e) * DD + d];
        } else if (n < 2 * NQK) {
            int nn = n - NQK;
            int h = nn >> 6, d = nn & 63;
            w = Wk[(h * EE + e) * DD + d];
        } else {
            int nn = n - 2 * NQK;
            int h = nn >> 4, r = nn & 15;
            w = Wvd[(h * EE + e) * RR + r];
        }
        g_Wh[idx] = __float2half(w);
    }
    if (idx < NTOT) {
        float bv;
        if (idx < NQK)          bv = bq[idx];
        else if (idx < 2 * NQK) bv = bk[idx - NQK];
        else                    bv = bvd[idx - 2 * NQK];
        g_ball[idx] = bv;
    }
}

// ---------------- fused QKV projection GEMM (fp16 m16n8k16) ----------------
// Block 128x128x16, 256 threads, warp tile 64x32.
#define AH 24    // halves per A smem row (16 + 8 pad) -> 12 words, conflict-free frags
#define BW 9     // words per B smem n-row (8 k-pairs + 1 pad)
__global__ void __launch_bounds__(256) qkv_gemm_kernel() {
    __shared__ __half   As[2][128 * AH];
    __shared__ uint32_t Bs[2][128 * BW];   // [n][k-pair] interleaved fp16 pairs

    const int m0 = blockIdx.y * 128;
    const int n0 = blockIdx.x * 128;
    const int tid = threadIdx.x;
    const int lane = tid & 31;
    const int warp = tid >> 5;
    const int lg = lane >> 2;
    const int lr = lane & 3;
    const int wm = (warp >> 2) * 64;
    const int wn = (warp & 3) * 32;

    const int am = tid >> 1;          // A row 0..127
    const int ak = (tid & 1) * 8;     // A col base (halves)
    const int bk2 = tid & 7;          // B k-pair 0..7   (tid < 128)
    const int bn = (tid >> 3) * 8;    // B n base 0..120 (tid < 128)

    float c[4][4][4];
#pragma unroll
    for (int i = 0; i < 4; ++i)
#pragma unroll
        for (int j = 0; j < 4; ++j)
#pragma unroll
            for (int e = 0; e < 4; ++e) c[i][j][e] = 0.f;

    uint4 pa, pb0, pb1;
    pa = *(const uint4*)(g_Xh + (size_t)(m0 + am) * EE + ak);
    if (tid < 128) {
        pb0 = *(const uint4*)(g_Wh + (size_t)(2 * bk2) * NTOT + n0 + bn);
        pb1 = *(const uint4*)(g_Wh + (size_t)(2 * bk2 + 1) * NTOT + n0 + bn);
    }
    {
        *(uint4*)(&As[0][am * AH + ak]) = pa;
        if (tid < 128) {
            uint32_t* bdst = &Bs[0][0];
            bdst[(bn + 0) * BW + bk2] = prmt(pb0.x, pb1.x, 0x5410);
            bdst[(bn + 1) * BW + bk2] = prmt(pb0.x, pb1.x, 0x7632);
            bdst[(bn + 2) * BW + bk2] = prmt(pb0.y, pb1.y, 0x5410);
            bdst[(bn + 3) * BW + bk2] = prmt(pb0.y, pb1.y, 0x7632);
            bdst[(bn + 4) * BW + bk2] = prmt(pb0.z, pb1.z, 0x5410);
            bdst[(bn + 5) * BW + bk2] = prmt(pb0.z, pb1.z, 0x7632);
            bdst[(bn + 6) * BW + bk2] = prmt(pb0.w, pb1.w, 0x5410);
            bdst[(bn + 7) * BW + bk2] = prmt(pb0.w, pb1.w, 0x7632);
        }
    }
    __syncthreads();

    const int NK = EE / 16;   // 64
    for (int kt = 0; kt < NK; ++kt) {
        const int cur = kt & 1;
        if (kt + 1 < NK) {
            int k0 = (kt + 1) * 16;
            pa = *(const uint4*)(g_Xh + (size_t)(m0 + am) * EE + k0 + ak);
            if (tid < 128) {
                pb0 = *(const uint4*)(g_Wh + (size_t)(k0 + 2 * bk2) * NTOT + n0 + bn);
                pb1 = *(const uint4*)(g_Wh + (size_t)(k0 + 2 * bk2 + 1) * NTOT + n0 + bn);
            }
        }

        // fragments + 16 mma
        uint32_t a[4][4];
#pragma unroll
        for (int mt = 0; mt < 4; ++mt) {
            int row = wm + mt * 16;
            a[mt][0] = *(uint32_t*)(&As[cur][(row + lg) * AH + 2 * lr]);
            a[mt][1] = *(uint32_t*)(&As[cur][(row + lg + 8) * AH + 2 * lr]);
            a[mt][2] = *(uint32_t*)(&As[cur][(row + lg) * AH + 2 * lr + 8]);
            a[mt][3] = *(uint32_t*)(&As[cur][(row + lg + 8) * AH + 2 * lr + 8]);
        }
        uint32_t b[4][2];
#pragma unroll
        for (int nt = 0; nt < 4; ++nt) {
            int col = wn + nt * 8 + lg;
            b[nt][0] = Bs[cur][col * BW + lr];
            b[nt][1] = Bs[cur][col * BW + lr + 4];
        }
#pragma unroll
        for (int mt = 0; mt < 4; ++mt)
#pragma unroll
            for (int nt = 0; nt < 4; ++nt)
                mma_f16(c[mt][nt], a[mt], b[nt][0], b[nt][1]);

        if (kt + 1 < NK) {
            int nxt = cur ^ 1;
            *(uint4*)(&As[nxt][am * AH + ak]) = pa;
            if (tid < 128) {
                uint32_t* bdst = &Bs[nxt][0];
                bdst[(bn + 0) * BW + bk2] = prmt(pb0.x, pb1.x, 0x5410);
                bdst[(bn + 1) * BW + bk2] = prmt(pb0.x, pb1.x, 0x7632);
                bdst[(bn + 2) * BW + bk2] = prmt(pb0.y, pb1.y, 0x5410);
                bdst[(bn + 3) * BW + bk2] = prmt(pb0.y, pb1.y, 0x7632);
                bdst[(bn + 4) * BW + bk2] = prmt(pb0.z, pb1.z, 0x5410);
                bdst[(bn + 5) * BW + bk2] = prmt(pb0.z, pb1.z, 0x7632);
                bdst[(bn + 6) * BW + bk2] = prmt(pb0.w, pb1.w, 0x5410);
                bdst[(bn + 7) * BW + bk2] = prmt(pb0.w, pb1.w, 0x7632);
            }
        }
        __syncthreads();
    }

    // epilogue: bias (+ q scale), convert, scatter
#pragma unroll
    for (int mt = 0; mt < 4; ++mt) {
#pragma unroll
        for (int e2 = 0; e2 < 2; ++e2) {
            int m = m0 + wm + mt * 16 + lg + e2 * 8;
            int b_ = m >> 11;
            int s = m & 2047;
#pragma unroll
            for (int nt = 0; nt < 4; ++nt) {
                int n = n0 + wn + nt * 8 + 2 * lr;
                float2 bias = *(const float2*)(g_ball + n);
                float vx = c[mt][nt][e2 * 2 + 0] + bias.x;
                float vy = c[mt][nt][e2 * 2 + 1] + bias.y;
                if (n < NQK) {
                    int h = n >> 6, d = n & 63;
                    uint32_t w = f16x2(vy * QSCALE, vx * QSCALE);
                    *(uint32_t*)(g_qh + (((size_t)(b_ * HH + h)) * SS + s) * DD + d) = w;
                } else if (n < 2 * NQK) {
                    int nn = n - NQK;
                    int h = nn >> 6, d = nn & 63;
                    uint32_t w = f16x2(vy, vx);
                    *(uint32_t*)(g_kh + (((size_t)(b_ * HH + h)) * SS + s) * DD + d) = w;
                } else {
                    int nn = n - 2 * NQK;
                    int h = nn >> 4, r = nn & 15;
                    *(float2*)(g_vd + (((size_t)(b_ * HH + h)) * SS + s) * RR + r) = make_float2(vx, vy);
                }
            }
        }
    }
}

// ---------------- V up-projection -> fp16 ----------------
__global__ void vu_kernel(const float* __restrict__ Wvu, const float* __restrict__ bvu) {
    int g = blockIdx.x * 4 + threadIdx.y;
    int d = threadIdx.x;
    int h = (g >> 11) & 15;
    float acc = bvu[h * DD + d];
    const float* vdrow = g_vd + (size_t)g * RR;
    const float* w = Wvu + (size_t)h * RR * DD;
#pragma unroll
    for (int r = 0; r < RR; ++r) acc += vdrow[r] * w[r * DD + d];
    g_vh[(size_t)g * DD + d] = __float2half(acc);
}

// ---------------- flash attention: fp16 m16n8k16 + ldmatrix ----------------
#define KVH 72   // halves per smem row (64 + 8 pad)
__global__ void __launch_bounds__(128) attn_kernel(float* __restrict__ out) {
    __shared__ __half Ks[64 * KVH];   // [key][d]; also Q staging
    __shared__ __half Vs[64 * KVH];   // [key][d]

    const int qt = blockIdx.x;
    const int bh = blockIdx.y;
    const int q0 = qt * 64;
    const __half* qb = g_qh + (size_t)bh * SS * DD;
    const __half* kb = g_kh + (size_t)bh * SS * DD;
    const __half* vb = g_vh + (size_t)bh * SS * DD;

    const int tid = threadIdx.x;
    const int lane = tid & 31;
    const int warp = tid >> 5;
    const int lg = lane >> 2;
    const int lr = lane & 3;

    const uint32_t ksbase = (uint32_t)__cvta_generic_to_shared(Ks);
    const uint32_t vsbase = (uint32_t)__cvta_generic_to_shared(Vs);
    // lane offsets (bytes): row-split ±8 pattern (Q A-frags / V trans B-frags)
    const uint32_t laneoff_q = (uint32_t)(((lane & 7) + ((lane >> 3) & 1) * 8) * (KVH * 2) + (lane >> 4) * 16);
    // all-rows-same pattern (K non-trans B-frags)
    const uint32_t laneoff_k = (uint32_t)((lane & 7) * (KVH * 2) + (lane >> 3) * 16);

    // ---- stage Q (pure copy; already scaled fp16) ----
#pragma unroll
    for (int it = 0; it < 4; ++it) {
        int idx = tid + it * 128;
        int r = idx >> 3;
        int c8 = (idx & 7) * 8;
        *(uint4*)(Ks + r * KVH + c8) = *(const uint4*)(qb + (size_t)(q0 + r) * DD + c8);
    }
    __syncthreads();

    uint32_t aq[4][4];
    {
        uint32_t qa = ksbase + (uint32_t)(warp * 16 * (KVH * 2)) + laneoff_q;
#pragma unroll
        for (int kc = 0; kc < 4; ++kc)
            ldsm4(aq[kc][0], aq[kc][1], aq[kc][2], aq[kc][3], qa + kc * 32);
    }

    float o[8][4];
    float m0r = -1e30f, m1r = -1e30f, l0r = 0.f, l1r = 0.f;
#pragma unroll
    for (int j = 0; j < 8; ++j)
#pragma unroll
        for (int e = 0; e < 4; ++e) o[j][e] = 0.f;

    for (int t = qt; t < SS / 64; ++t) {
        __syncthreads();
        // stage K and V (pure copies)
#pragma unroll
        for (int it = 0; it < 4; ++it) {
            int idx = tid + it * 128;
            int r = idx >> 3;
            int c8 = (idx & 7) * 8;
            *(uint4*)(Ks + r * KVH + c8) = *(const uint4*)(kb + (size_t)(t * 64 + r) * DD + c8);
            *(uint4*)(Vs + r * KVH + c8) = *(const uint4*)(vb + (size_t)(t * 64 + r) * DD + c8);
        }
        __syncthreads();

        // ---- S = Q @ K^T ----
        float s[8][4];
#pragma unroll
        for (int j = 0; j < 8; ++j)
#pragma unroll
            for (int e = 0; e < 4; ++e) s[j][e] = 0.f;

#pragma unroll
        for (int j = 0; j < 8; ++j) {
            uint32_t kaddr = ksbase + (uint32_t)(j * 8 * (KVH * 2)) + laneoff_k;
#pragma unroll
            for (int kcp = 0; kcp < 2; ++kcp) {
                uint32_t r0, r1, r2, r3;
                ldsm4(r0, r1, r2, r3, kaddr + kcp * 64);
                mma_f16(s[j], aq[2 * kcp], r0, r1);
                mma_f16(s[j], aq[2 * kcp + 1], r2, r3);
            }
        }

        // ---- reverse-causal mask (diagonal tile only) ----
        if (t == qt) {
            int qr0 = q0 + warp * 16 + lg;
#pragma unroll
            for (int j = 0; j < 8; ++j) {
                int kg = t * 64 + j * 8 + lr * 2;
                if (kg < qr0)          s[j][0] = -1e30f;
                if (kg + 1 < qr0)      s[j][1] = -1e30f;
                if (kg < qr0 + 8)      s[j][2] = -1e30f;
                if (kg + 1 < qr0 + 8)  s[j][3] = -1e30f;
            }
        }

        // ---- online softmax (base-2) ----
        float rm0 = -1e30f, rm1 = -1e30f;
#pragma unroll
        for (int j = 0; j < 8; ++j) {
            rm0 = fmaxf(rm0, fmaxf(s[j][0], s[j][1]));
            rm1 = fmaxf(rm1, fmaxf(s[j][2], s[j][3]));
        }
        rm0 = fmaxf(rm0, __shfl_xor_sync(0xffffffffu, rm0, 1));
        rm0 = fmaxf(rm0, __shfl_xor_sync(0xffffffffu, rm0, 2));
        rm1 = fmaxf(rm1, __shfl_xor_sync(0xffffffffu, rm1, 1));
        rm1 = fmaxf(rm1, __shfl_xor_sync(0xffffffffu, rm1, 2));

        float mn0 = fmaxf(m0r, rm0);
        float mn1 = fmaxf(m1r, rm1);
        float al0 = ex2(m0r - mn0);
        float al1 = ex2(m1r - mn1);
        m0r = mn0; m1r = mn1;

        float rs0 = 0.f, rs1 = 0.f;
        uint32_t p2[8][2];
#pragma unroll
        for (int j = 0; j < 8; ++j) {
            float p0 = ex2(s[j][0] - mn0);
            float p1 = ex2(s[j][1] - mn0);
            float p2v = ex2(s[j][2] - mn1);
            float p3 = ex2(s[j][3] - mn1);
            rs0 += p0 + p1;
            rs1 += p2v + p3;
            p2[j][0] = f16x2(p1, p0);    // {lo=c0, hi=c1} -> a-reg rows lg
            p2[j][1] = f16x2(p3, p2v);   // {lo=c2, hi=c3} -> a-reg rows lg+8
        }
        rs0 += __shfl_xor_sync(0xffffffffu, rs0, 1);
        rs0 += __shfl_xor_sync(0xffffffffu, rs0, 2);
        rs1 += __shfl_xor_sync(0xffffffffu, rs1, 1);
        rs1 += __shfl_xor_sync(0xffffffffu, rs1, 2);
        l0r = l0r * al0 + rs0;
        l1r = l1r * al1 + rs1;

#pragma unroll
        for (int j = 0; j < 8; ++j) {
            o[j][0] *= al0; o[j][1] *= al0;
            o[j][2] *= al1; o[j][3] *= al1;
        }

        // ---- O += P @ V  (A from packed C-frags, B via ldmatrix.trans) ----
#pragma unroll
        for (int g = 0; g < 4; ++g) {
            uint32_t a[4];
            a[0] = p2[2 * g][0];
            a[1] = p2[2 * g][1];
            a[2] = p2[2 * g + 1][0];
            a[3] = p2[2 * g + 1][1];
            uint32_t vaddr = vsbase + (uint32_t)(g * 16 * (KVH * 2)) + laneoff_q;
#pragma unroll
            for (int dp = 0; dp < 4; ++dp) {
                uint32_t r0, r1, r2, r3;
                ldsm4t(r0, r1, r2, r3, vaddr + dp * 32);
                mma_f16(o[2 * dp], a, r0, r1);
                mma_f16(o[2 * dp + 1], a, r2, r3);
            }
        }
    }

    // ---- write normalized output ----
    int h = bh % HH, b = bh / HH;
    float inv0 = 1.f / l0r;
    float inv1 = 1.f / l1r;
    int qr0 = q0 + warp * 16 + lg;
#pragma unroll
    for (int j2 = 0; j2 < 8; ++j2) {
        int d = j2 * 8 + lr * 2;
        float2 v0 = make_float2(o[j2][0] * inv0, o[j2][1] * inv0);
        float2 v1 = make_float2(o[j2][2] * inv1, o[j2][3] * inv1);
        *(float2*)(out + (((size_t)(b * SS + qr0)) * HH + h) * DD + d) = v0;
        *(float2*)(out + (((size_t)(b * SS + qr0 + 8)) * HH + h) * DD + d) = v1;
    }
}

// ---------------- launcher ----------------
extern "C" void kernel_launch(void* const* d_in, const int* in_sizes, int n_in,
                              void* d_out, int out_size) {
    const float* x   = (const float*)d_in[0];
    const float* Wq  = (const float*)d_in[1];
    const float* bq  = (const float*)d_in[2];
    const float* Wk  = (const float*)d_in[3];
    const float* bk  = (const float*)d_in[4];
    const float* Wvd = (const float*)d_in[5];
    const float* bvd = (const float*)d_in[6];
    const float* Wvu = (const float*)d_in[7];
    const float* bvu = (const float*)d_in[8];
    float* out = (float*)d_out;

    {
        int n8 = MROWS * EE / 8;   // 524288
        xh_kernel<<<n8 / 256, 256>>>(x);
    }
    {
        int total = EE * NTOT;
        pack_kernel<<<(total + 255) / 256, 256>>>(Wq, bq, Wk, bk, Wvd, bvd);
    }
    {
        dim3 grid(NTOT / 128, MROWS / 128);  // (18, 32)
        qkv_gemm_kernel<<<grid, 256>>>();
    }
    {
        dim3 block(64, 4);
        vu_kernel<<<(BH * SS) / 4, block>>>(Wvu, bvu);
    }
    {
        dim3 grid(SS / 64, BH);  // (32, 32)
        attn_kernel<<<grid, 128>>>(out);
    }
}

// round 8
// speedup vs baseline: 1.7974x; 1.4138x over previous
#include <cuda_runtime.h>
#include <cuda_fp16.h>
#include <cstdint>

// Problem constants
#define BB 2
#define SS 2048
#define EE 1024
#define HH 16
#define DD 64
#define RR 16
#define BH (BB*HH)          // 32
#define NQK (HH*DD)         // 1024
#define NTOT (2*NQK + HH*RR) // 2304
#define MROWS (BB*SS)       // 4096

// 1/sqrt(E) * log2(e)
#define QSCALE (0.03125f * 1.4426950408889634f)

// ---------------- device scratch ----------------
__device__ __half g_Wh[EE * NTOT];           // packed weights [k][n] fp16
__device__ __half g_Xh[MROWS * EE];          // x in fp16
__device__ float  g_ball[NTOT];
__device__ __half g_qh[BH * SS * DD];        // (b,h,s,d) pre-scaled fp16
__device__ __half g_kh[BH * SS * DD];
__device__ float  g_vd[BH * SS * RR];
__device__ __half g_vh[BH * SS * DD];

// ---------------- helpers ----------------
__device__ __forceinline__ float ex2(float x) {
    float r;
    asm("ex2.approx.f32 %0, %1;" : "=f"(r) : "f"(x));
    return r;
}

__device__ __forceinline__ uint32_t f16x2(float hi, float lo) {
    uint32_t r;
    asm("cvt.rn.f16x2.f32 %0, %1, %2;" : "=r"(r) : "f"(hi), "f"(lo));
    return r;
}

__device__ __forceinline__ uint32_t prmt(uint32_t a, uint32_t b, uint32_t sel) {
    uint32_t r;
    asm("prmt.b32 %0, %1, %2, %3;" : "=r"(r) : "r"(a), "r"(b), "r"(sel));
    return r;
}

__device__ __forceinline__ void mma_f16(float c[4], const uint32_t a[4], uint32_t b0, uint32_t b1) {
    asm volatile(
        "mma.sync.aligned.m16n8k16.row.col.f32.f16.f16.f32 "
        "{%0,%1,%2,%3}, {%4,%5,%6,%7}, {%8,%9}, {%0,%1,%2,%3};"
        : "+f"(c[0]), "+f"(c[1]), "+f"(c[2]), "+f"(c[3])
        : "r"(a[0]), "r"(a[1]), "r"(a[2]), "r"(a[3]), "r"(b0), "r"(b1));
}

__device__ __forceinline__ void ldsm4(uint32_t& r0, uint32_t& r1, uint32_t& r2, uint32_t& r3, uint32_t addr) {
    asm volatile("ldmatrix.sync.aligned.m8n8.x4.shared.b16 {%0,%1,%2,%3}, [%4];"
                 : "=r"(r0), "=r"(r1), "=r"(r2), "=r"(r3) : "r"(addr));
}

__device__ __forceinline__ void ldsm4t(uint32_t& r0, uint32_t& r1, uint32_t& r2, uint32_t& r3, uint32_t addr) {
    asm volatile("ldmatrix.sync.aligned.m8n8.x4.trans.shared.b16 {%0,%1,%2,%3}, [%4];"
                 : "=r"(r0), "=r"(r1), "=r"(r2), "=r"(r3) : "r"(addr));
}

__device__ __forceinline__ void cp16(uint32_t smem, const void* gptr) {
    asm volatile("cp.async.cg.shared.global [%0], [%1], 16;" :: "r"(smem), "l"(gptr));
}
#define CP_COMMIT() asm volatile("cp.async.commit_group;")
#define CP_WAIT1()  asm volatile("cp.async.wait_group 1;")
#define CP_WAIT0()  asm volatile("cp.async.wait_group 0;")

// ---------------- X -> fp16 ----------------
__global__ void xh_kernel(const float* __restrict__ X) {
    int g = blockIdx.x * blockDim.x + threadIdx.x;
    int idx = g * 8;
    float4 f0 = *(const float4*)(X + idx);
    float4 f1 = *(const float4*)(X + idx + 4);
    uint4 u;
    u.x = f16x2(f0.y, f0.x);
    u.y = f16x2(f0.w, f0.z);
    u.z = f16x2(f1.y, f1.x);
    u.w = f16x2(f1.w, f1.z);
    *(uint4*)(g_Xh + idx) = u;
}

// ---------------- pack weights -> fp16 [k][n], 8 elems/thread ----------------
__global__ void pack_kernel(const float* __restrict__ Wq, const float* __restrict__ bq,
                            const float* __restrict__ Wk, const float* __restrict__ bk,
                            const float* __restrict__ Wvd, const float* __restrict__ bvd) {
    int t8 = blockIdx.x * blockDim.x + threadIdx.x;   // 0..294911
    int e = t8 / (NTOT / 8);
    int n = (t8 % (NTOT / 8)) * 8;
    const float* src;
    if (n < NQK) {
        int h = n >> 6, d = n & 63;
        src = Wq + ((size_t)h * EE + e) * DD + d;
    } else if (n < 2 * NQK) {
        int nn = n - NQK;
        int h = nn >> 6, d = nn & 63;
        src = Wk + ((size_t)h * EE + e) * DD + d;
    } else {
        int nn = n - 2 * NQK;
        int h = nn >> 4, r = nn & 15;
        src = Wvd + ((size_t)h * EE + e) * RR + r;
    }
    float4 f0 = *(const float4*)src;
    float4 f1 = *(const float4*)(src + 4);
    uint4 u;
    u.x = f16x2(f0.y, f0.x);
    u.y = f16x2(f0.w, f0.z);
    u.z = f16x2(f1.y, f1.x);
    u.w = f16x2(f1.w, f1.z);
    *(uint4*)(g_Wh + (size_t)e * NTOT + n) = u;

    if (t8 < NTOT / 8) {
        int nb = t8 * 8;
        const float* bs;
        if (nb < NQK)          bs = bq + nb;
        else if (nb < 2 * NQK) bs = bk + (nb - NQK);
        else                   bs = bvd + (nb - 2 * NQK);
        float4 b0 = *(const float4*)bs;
        float4 b1 = *(const float4*)(bs + 4);
        *(float4*)(g_ball + nb)     = b0;
        *(float4*)(g_ball + nb + 4) = b1;
    }
}

// ---------------- fused QKV projection GEMM (fp16 m16n8k16) ----------------
#define AH 24
#define BW 9
__global__ void __launch_bounds__(256) qkv_gemm_kernel() {
    __shared__ __half   As[2][128 * AH];
    __shared__ uint32_t Bs[2][128 * BW];

    const int m0 = blockIdx.y * 128;
    const int n0 = blockIdx.x * 128;
    const int tid = threadIdx.x;
    const int lane = tid & 31;
    const int warp = tid >> 5;
    const int lg = lane >> 2;
    const int lr = lane & 3;
    const int wm = (warp >> 2) * 64;
    const int wn = (warp & 3) * 32;

    const int am = tid >> 1;
    const int ak = (tid & 1) * 8;
    const int bk2 = tid & 7;
    const int bn = (tid >> 3) * 8;

    float c[4][4][4];
#pragma unroll
    for (int i = 0; i < 4; ++i)
#pragma unroll
        for (int j = 0; j < 4; ++j)
#pragma unroll
            for (int e = 0; e < 4; ++e) c[i][j][e] = 0.f;

    uint4 pa, pb0, pb1;
    pa = *(const uint4*)(g_Xh + (size_t)(m0 + am) * EE + ak);
    if (tid < 128) {
        pb0 = *(const uint4*)(g_Wh + (size_t)(2 * bk2) * NTOT + n0 + bn);
        pb1 = *(const uint4*)(g_Wh + (size_t)(2 * bk2 + 1) * NTOT + n0 + bn);
    }
    {
        *(uint4*)(&As[0][am * AH + ak]) = pa;
        if (tid < 128) {
            uint32_t* bdst = &Bs[0][0];
            bdst[(bn + 0) * BW + bk2] = prmt(pb0.x, pb1.x, 0x5410);
            bdst[(bn + 1) * BW + bk2] = prmt(pb0.x, pb1.x, 0x7632);
            bdst[(bn + 2) * BW + bk2] = prmt(pb0.y, pb1.y, 0x5410);
            bdst[(bn + 3) * BW + bk2] = prmt(pb0.y, pb1.y, 0x7632);
            bdst[(bn + 4) * BW + bk2] = prmt(pb0.z, pb1.z, 0x5410);
            bdst[(bn + 5) * BW + bk2] = prmt(pb0.z, pb1.z, 0x7632);
            bdst[(bn + 6) * BW + bk2] = prmt(pb0.w, pb1.w, 0x5410);
            bdst[(bn + 7) * BW + bk2] = prmt(pb0.w, pb1.w, 0x7632);
        }
    }
    __syncthreads();

    const int NK = EE / 16;
    for (int kt = 0; kt < NK; ++kt) {
        const int cur = kt & 1;
        if (kt + 1 < NK) {
            int k0 = (kt + 1) * 16;
            pa = *(const uint4*)(g_Xh + (size_t)(m0 + am) * EE + k0 + ak);
            if (tid < 128) {
                pb0 = *(const uint4*)(g_Wh + (size_t)(k0 + 2 * bk2) * NTOT + n0 + bn);
                pb1 = *(const uint4*)(g_Wh + (size_t)(k0 + 2 * bk2 + 1) * NTOT + n0 + bn);
            }
        }

        uint32_t a[4][4];
#pragma unroll
        for (int mt = 0; mt < 4; ++mt) {
            int row = wm + mt * 16;
            a[mt][0] = *(uint32_t*)(&As[cur][(row + lg) * AH + 2 * lr]);
            a[mt][1] = *(uint32_t*)(&As[cur][(row + lg + 8) * AH + 2 * lr]);
            a[mt][2] = *(uint32_t*)(&As[cur][(row + lg) * AH + 2 * lr + 8]);
            a[mt][3] = *(uint32_t*)(&As[cur][(row + lg + 8) * AH + 2 * lr + 8]);
        }
        uint32_t b[4][2];
#pragma unroll
        for (int nt = 0; nt < 4; ++nt) {
            int col = wn + nt * 8 + lg;
            b[nt][0] = Bs[cur][col * BW + lr];
            b[nt][1] = Bs[cur][col * BW + lr + 4];
        }
#pragma unroll
        for (int mt = 0; mt < 4; ++mt)
#pragma unroll
            for (int nt = 0; nt < 4; ++nt)
                mma_f16(c[mt][nt], a[mt], b[nt][0], b[nt][1]);

        if (kt + 1 < NK) {
            int nxt = cur ^ 1;
            *(uint4*)(&As[nxt][am * AH + ak]) = pa;
            if (tid < 128) {
                uint32_t* bdst = &Bs[nxt][0];
                bdst[(bn + 0) * BW + bk2] = prmt(pb0.x, pb1.x, 0x5410);
                bdst[(bn + 1) * BW + bk2] = prmt(pb0.x, pb1.x, 0x7632);
                bdst[(bn + 2) * BW + bk2] = prmt(pb0.y, pb1.y, 0x5410);
                bdst[(bn + 3) * BW + bk2] = prmt(pb0.y, pb1.y, 0x7632);
                bdst[(bn + 4) * BW + bk2] = prmt(pb0.z, pb1.z, 0x5410);
                bdst[(bn + 5) * BW + bk2] = prmt(pb0.z, pb1.z, 0x7632);
                bdst[(bn + 6) * BW + bk2] = prmt(pb0.w, pb1.w, 0x5410);
                bdst[(bn + 7) * BW + bk2] = prmt(pb0.w, pb1.w, 0x7632);
            }
        }
        __syncthreads();
    }

#pragma unroll
    for (int mt = 0; mt < 4; ++mt) {
#pragma unroll
        for (int e2 = 0; e2 < 2; ++e2) {
            int m = m0 + wm + mt * 16 + lg + e2 * 8;
            int b_ = m >> 11;
            int s = m & 2047;
#pragma unroll
            for (int nt = 0; nt < 4; ++nt) {
                int n = n0 + wn + nt * 8 + 2 * lr;
                float2 bias = *(const float2*)(g_ball + n);
                float vx = c[mt][nt][e2 * 2 + 0] + bias.x;
                float vy = c[mt][nt][e2 * 2 + 1] + bias.y;
                if (n < NQK) {
                    int h = n >> 6, d = n & 63;
                    uint32_t w = f16x2(vy * QSCALE, vx * QSCALE);
                    *(uint32_t*)(g_qh + (((size_t)(b_ * HH + h)) * SS + s) * DD + d) = w;
                } else if (n < 2 * NQK) {
                    int nn = n - NQK;
                    int h = nn >> 6, d = nn & 63;
                    uint32_t w = f16x2(vy, vx);
                    *(uint32_t*)(g_kh + (((size_t)(b_ * HH + h)) * SS + s) * DD + d) = w;
                } else {
                    int nn = n - 2 * NQK;
                    int h = nn >> 4, r = nn & 15;
                    *(float2*)(g_vd + (((size_t)(b_ * HH + h)) * SS + s) * RR + r) = make_float2(vx, vy);
                }
            }
        }
    }
}

// ---------------- V up-projection -> fp16 (2 rows x 4 d per thread) ----------------
__global__ void __launch_bounds__(256) vu_kernel(const float* __restrict__ Wvu,
                                                 const float* __restrict__ bvu) {
    const int tid = threadIdx.x;
    const int pairIdx = blockIdx.x * 16 + (tid >> 4);  // 16 row-pairs per block
    const int g0 = pairIdx * 2;
    const int dx = (tid & 15) * 4;
    const int h = (g0 >> 11) & 15;

    const float* w = Wvu + (size_t)h * RR * DD + dx;
    const float* vd0p = g_vd + (size_t)g0 * RR;

    float vr0[RR], vr1[RR];
#pragma unroll
    for (int i = 0; i < 4; ++i) {
        *(float4*)(vr0 + i * 4) = *(const float4*)(vd0p + i * 4);
        *(float4*)(vr1 + i * 4) = *(const float4*)(vd0p + RR + i * 4);
    }

    float4 b4 = *(const float4*)(bvu + h * DD + dx);
    float4 a0 = b4, a1 = b4;
#pragma unroll
    for (int r = 0; r < RR; ++r) {
        float4 w4 = *(const float4*)(w + r * DD);
        a0.x += vr0[r] * w4.x; a0.y += vr0[r] * w4.y;
        a0.z += vr0[r] * w4.z; a0.w += vr0[r] * w4.w;
        a1.x += vr1[r] * w4.x; a1.y += vr1[r] * w4.y;
        a1.z += vr1[r] * w4.z; a1.w += vr1[r] * w4.w;
    }
    uint2 o0 = make_uint2(f16x2(a0.y, a0.x), f16x2(a0.w, a0.z));
    uint2 o1 = make_uint2(f16x2(a1.y, a1.x), f16x2(a1.w, a1.z));
    *(uint2*)(g_vh + (size_t)g0 * DD + dx)       = o0;
    *(uint2*)(g_vh + (size_t)(g0 + 1) * DD + dx) = o1;
}

// ---------------- flash attention: fp16 m16n8k16 + ldmatrix + cp.async ----------------
#define KVH 72                 // halves per smem row (64 + 8 pad); 144B, 16B-aligned
#define KVBYTES (64 * KVH * 2) // 9216 bytes per buffer
__global__ void __launch_bounds__(128) attn_kernel(float* __restrict__ out) {
    __shared__ __half Ks[2][64 * KVH];
    __shared__ __half Vs[2][64 * KVH];

    const int qt = blockIdx.x;
    const int bh = blockIdx.y;
    const int q0 = qt * 64;
    const __half* qb = g_qh + (size_t)bh * SS * DD;
    const __half* kb = g_kh + (size_t)bh * SS * DD;
    const __half* vb = g_vh + (size_t)bh * SS * DD;

    const int tid = threadIdx.x;
    const int lane = tid & 31;
    const int warp = tid >> 5;
    const int lg = lane >> 2;
    const int lr = lane & 3;

    const uint32_t ksbase = (uint32_t)__cvta_generic_to_shared(&Ks[0][0]);
    const uint32_t vsbase = (uint32_t)__cvta_generic_to_shared(&Vs[0][0]);
    const uint32_t laneoff_q = (uint32_t)(((lane & 7) + ((lane >> 3) & 1) * 8) * (KVH * 2) + (lane >> 4) * 16);
    const uint32_t laneoff_k = (uint32_t)((lane & 7) * (KVH * 2) + (lane >> 3) * 16);

    const int NT = SS / 64;

    // issue async load of tile t into buffer buf (K and V)
    auto issue_tile = [&](int buf, int t) {
        const __half* kbase = kb + (size_t)t * 64 * DD;
        const __half* vbase = vb + (size_t)t * 64 * DD;
        uint32_t kdst = ksbase + buf * KVBYTES;
        uint32_t vdst = vsbase + buf * KVBYTES;
#pragma unroll
        for (int it = 0; it < 4; ++it) {
            int idx = tid + it * 128;
            int r = idx >> 3;
            int c8 = (idx & 7) * 8;
            cp16(kdst + r * (KVH * 2) + c8 * 2, kbase + r * DD + c8);
            cp16(vdst + r * (KVH * 2) + c8 * 2, vbase + r * DD + c8);
        }
    };

    // prologue: async-load first tile into buf 0; stage Q through Vs[1]
    issue_tile(0, qt);
    CP_COMMIT();

#pragma unroll
    for (int it = 0; it < 4; ++it) {
        int idx = tid + it * 128;
        int r = idx >> 3;
        int c8 = (idx & 7) * 8;
        *(uint4*)(&Vs[1][r * KVH + c8]) = *(const uint4*)(qb + (size_t)(q0 + r) * DD + c8);
    }
    __syncthreads();

    uint32_t aq[4][4];
    {
        uint32_t qa = vsbase + KVBYTES + (uint32_t)(warp * 16 * (KVH * 2)) + laneoff_q;
#pragma unroll
        for (int kc = 0; kc < 4; ++kc)
            ldsm4(aq[kc][0], aq[kc][1], aq[kc][2], aq[kc][3], qa + kc * 32);
    }
    __syncthreads();

    float o[8][4];
    float m0r = -1e30f, m1r = -1e30f, l0r = 0.f, l1r = 0.f;
#pragma unroll
    for (int j = 0; j < 8; ++j)
#pragma unroll
        for (int e = 0; e < 4; ++e) o[j][e] = 0.f;

    for (int t = qt; t < NT; ++t) {
        const int cur = (t - qt) & 1;
        if (t + 1 < NT) {
            issue_tile(cur ^ 1, t + 1);
            CP_COMMIT();
            CP_WAIT1();
        } else {
            CP_WAIT0();
        }
        __syncthreads();

        const uint32_t kcur = ksbase + cur * KVBYTES;
        const uint32_t vcur = vsbase + cur * KVBYTES;

        // ---- S = Q @ K^T ----
        float s[8][4];
#pragma unroll
        for (int j = 0; j < 8; ++j)
#pragma unroll
            for (int e = 0; e < 4; ++e) s[j][e] = 0.f;

#pragma unroll
        for (int j = 0; j < 8; ++j) {
            uint32_t kaddr = kcur + (uint32_t)(j * 8 * (KVH * 2)) + laneoff_k;
#pragma unroll
            for (int kcp = 0; kcp < 2; ++kcp) {
                uint32_t r0, r1, r2, r3;
                ldsm4(r0, r1, r2, r3, kaddr + kcp * 64);
                mma_f16(s[j], aq[2 * kcp], r0, r1);
                mma_f16(s[j], aq[2 * kcp + 1], r2, r3);
            }
        }

        // ---- reverse-causal mask (diagonal tile only) ----
        if (t == qt) {
            int qr0 = q0 + warp * 16 + lg;
#pragma unroll
            for (int j = 0; j < 8; ++j) {
                int kg = t * 64 + j * 8 + lr * 2;
                if (kg < qr0)          s[j][0] = -1e30f;
                if (kg + 1 < qr0)      s[j][1] = -1e30f;
                if (kg < qr0 + 8)      s[j][2] = -1e30f;
                if (kg + 1 < qr0 + 8)  s[j][3] = -1e30f;
            }
        }

        // ---- online softmax (base-2) ----
        float rm0 = -1e30f, rm1 = -1e30f;
#pragma unroll
        for (int j = 0; j < 8; ++j) {
            rm0 = fmaxf(rm0, fmaxf(s[j][0], s[j][1]));
            rm1 = fmaxf(rm1, fmaxf(s[j][2], s[j][3]));
        }
        rm0 = fmaxf(rm0, __shfl_xor_sync(0xffffffffu, rm0, 1));
        rm0 = fmaxf(rm0, __shfl_xor_sync(0xffffffffu, rm0, 2));
        rm1 = fmaxf(rm1, __shfl_xor_sync(0xffffffffu, rm1, 1));
        rm1 = fmaxf(rm1, __shfl_xor_sync(0xffffffffu, rm1, 2));

        float mn0 = fmaxf(m0r, rm0);
        float mn1 = fmaxf(m1r, rm1);
        float al0 = ex2(m0r - mn0);
        float al1 = ex2(m1r - mn1);
        m0r = mn0; m1r = mn1;

        float rs0 = 0.f, rs1 = 0.f;
        uint32_t p2[8][2];
#pragma unroll
        for (int j = 0; j < 8; ++j) {
            float p0 = ex2(s[j][0] - mn0);
            float p1 = ex2(s[j][1] - mn0);
            float p2v = ex2(s[j][2] - mn1);
            float p3 = ex2(s[j][3] - mn1);
            rs0 += p0 + p1;
            rs1 += p2v + p3;
            p2[j][0] = f16x2(p1, p0);
            p2[j][1] = f16x2(p3, p2v);
        }
        rs0 += __shfl_xor_sync(0xffffffffu, rs0, 1);
        rs0 += __shfl_xor_sync(0xffffffffu, rs0, 2);
        rs1 += __shfl_xor_sync(0xffffffffu, rs1, 1);
        rs1 += __shfl_xor_sync(0xffffffffu, rs1, 2);
        l0r = l0r * al0 + rs0;
        l1r = l1r * al1 + rs1;

#pragma unroll
        for (int j = 0; j < 8; ++j) {
            o[j][0] *= al0; o[j][1] *= al0;
            o[j][2] *= al1; o[j][3] *= al1;
        }

        // ---- O += P @ V ----
#pragma unroll
        for (int g = 0; g < 4; ++g) {
            uint32_t a[4];
            a[0] = p2[2 * g][0];
            a[1] = p2[2 * g][1];
            a[2] = p2[2 * g + 1][0];
            a[3] = p2[2 * g + 1][1];
            uint32_t vaddr = vcur + (uint32_t)(g * 16 * (KVH * 2)) + laneoff_q;
#pragma unroll
            for (int dp = 0; dp < 4; ++dp) {
                uint32_t r0, r1, r2, r3;
                ldsm4t(r0, r1, r2, r3, vaddr + dp * 32);
                mma_f16(o[2 * dp], a, r0, r1);
                mma_f16(o[2 * dp + 1], a, r2, r3);
            }
        }
        __syncthreads();
    }

    // ---- write normalized output ----
    int h = bh % HH, b = bh / HH;
    float inv0 = 1.f / l0r;
    float inv1 = 1.f / l1r;
    int qr0 = q0 + warp * 16 + lg;
#pragma unroll
    for (int j2 = 0; j2 < 8; ++j2) {
        int d = j2 * 8 + lr * 2;
        float2 v0 = make_float2(o[j2][0] * inv0, o[j2][1] * inv0);
        float2 v1 = make_float2(o[j2][2] * inv1, o[j2][3] * inv1);
        *(float2*)(out + (((size_t)(b * SS + qr0)) * HH + h) * DD + d) = v0;
        *(float2*)(out + (((size_t)(b * SS + qr0 + 8)) * HH + h) * DD + d) = v1;
    }
}

// ---------------- launcher ----------------
extern "C" void kernel_launch(void* const* d_in, const int* in_sizes, int n_in,
                              void* d_out, int out_size) {
    const float* x   = (const float*)d_in[0];
    const float* Wq  = (const float*)d_in[1];
    const float* bq  = (const float*)d_in[2];
    const float* Wk  = (const float*)d_in[3];
    const float* bk  = (const float*)d_in[4];
    const float* Wvd = (const float*)d_in[5];
    const float* bvd = (const float*)d_in[6];
    const float* Wvu = (const float*)d_in[7];
    const float* bvu = (const float*)d_in[8];
    float* out = (float*)d_out;

    {
        int n8 = MROWS * EE / 8;
        xh_kernel<<<n8 / 256, 256>>>(x);
    }
    {
        int t8 = EE * NTOT / 8;   // 294912
        pack_kernel<<<t8 / 256, 256>>>(Wq, bq, Wk, bk, Wvd, bvd);
    }
    {
        dim3 grid(NTOT / 128, MROWS / 128);  // (18, 32)
        qkv_gemm_kernel<<<grid, 256>>>();
    }
    {
        vu_kernel<<<(BH * SS) / 32, 256>>>(Wvu, bvu);
    }
    {
        dim3 grid(SS / 64, BH);  // (32, 32)
        attn_kernel<<<grid, 128>>>(out);
    }
}

// round 9
// speedup vs baseline: 1.8150x; 1.0098x over previous
#include <cuda_runtime.h>
#include <cuda_fp16.h>
#include <cstdint>

// Problem constants
#define BB 2
#define SS 2048
#define EE 1024
#define HH 16
#define DD 64
#define RR 16
#define BH (BB*HH)          // 32
#define NQK (HH*DD)         // 1024
#define NTOT (2*NQK + HH*RR) // 2304
#define MROWS (BB*SS)       // 4096

// 1/sqrt(E) * log2(e)
#define QSCALE (0.03125f * 1.4426950408889634f)

// ---------------- device scratch ----------------
__device__ __half g_Wh[EE * NTOT];           // packed weights [k][n] fp16
__device__ __half g_Xh[MROWS * EE];          // x in fp16
__device__ float  g_ball[NTOT];
__device__ __half g_qh[BH * SS * DD];        // (b,h,s,d) pre-scaled fp16
__device__ __half g_kh[BH * SS * DD];
__device__ __half g_vdh[BH * SS * RR];       // vd in fp16
__device__ __half g_vh[BH * SS * DD];

// ---------------- helpers ----------------
__device__ __forceinline__ float ex2(float x) {
    float r;
    asm("ex2.approx.f32 %0, %1;" : "=f"(r) : "f"(x));
    return r;
}

__device__ __forceinline__ uint32_t f16x2(float hi, float lo) {
    uint32_t r;
    asm("cvt.rn.f16x2.f32 %0, %1, %2;" : "=r"(r) : "f"(hi), "f"(lo));
    return r;
}

__device__ __forceinline__ uint32_t prmt(uint32_t a, uint32_t b, uint32_t sel) {
    uint32_t r;
    asm("prmt.b32 %0, %1, %2, %3;" : "=r"(r) : "r"(a), "r"(b), "r"(sel));
    return r;
}

__device__ __forceinline__ void mma_f16(float c[4], const uint32_t a[4], uint32_t b0, uint32_t b1) {
    asm volatile(
        "mma.sync.aligned.m16n8k16.row.col.f32.f16.f16.f32 "
        "{%0,%1,%2,%3}, {%4,%5,%6,%7}, {%8,%9}, {%0,%1,%2,%3};"
        : "+f"(c[0]), "+f"(c[1]), "+f"(c[2]), "+f"(c[3])
        : "r"(a[0]), "r"(a[1]), "r"(a[2]), "r"(a[3]), "r"(b0), "r"(b1));
}

__device__ __forceinline__ void ldsm4(uint32_t& r0, uint32_t& r1, uint32_t& r2, uint32_t& r3, uint32_t addr) {
    asm volatile("ldmatrix.sync.aligned.m8n8.x4.shared.b16 {%0,%1,%2,%3}, [%4];"
                 : "=r"(r0), "=r"(r1), "=r"(r2), "=r"(r3) : "r"(addr));
}

__device__ __forceinline__ void ldsm4t(uint32_t& r0, uint32_t& r1, uint32_t& r2, uint32_t& r3, uint32_t addr) {
    asm volatile("ldmatrix.sync.aligned.m8n8.x4.trans.shared.b16 {%0,%1,%2,%3}, [%4];"
                 : "=r"(r0), "=r"(r1), "=r"(r2), "=r"(r3) : "r"(addr));
}

__device__ __forceinline__ void cp16(uint32_t smem, const void* gptr) {
    asm volatile("cp.async.cg.shared.global [%0], [%1], 16;" :: "r"(smem), "l"(gptr));
}
#define CP_COMMIT() asm volatile("cp.async.commit_group;")
#define CP_WAIT1()  asm volatile("cp.async.wait_group 1;")
#define CP_WAIT0()  asm volatile("cp.async.wait_group 0;")

// ---------------- X -> fp16 ----------------
__global__ void xh_kernel(const float* __restrict__ X) {
    int g = blockIdx.x * blockDim.x + threadIdx.x;
    int idx = g * 8;
    float4 f0 = *(const float4*)(X + idx);
    float4 f1 = *(const float4*)(X + idx + 4);
    uint4 u;
    u.x = f16x2(f0.y, f0.x);
    u.y = f16x2(f0.w, f0.z);
    u.z = f16x2(f1.y, f1.x);
    u.w = f16x2(f1.w, f1.z);
    *(uint4*)(g_Xh + idx) = u;
}

// ---------------- pack weights -> fp16 [k][n], 8 elems/thread ----------------
__global__ void pack_kernel(const float* __restrict__ Wq, const float* __restrict__ bq,
                            const float* __restrict__ Wk, const float* __restrict__ bk,
                            const float* __restrict__ Wvd, const float* __restrict__ bvd) {
    int t8 = blockIdx.x * blockDim.x + threadIdx.x;
    int e = t8 / (NTOT / 8);
    int n = (t8 % (NTOT / 8)) * 8;
    const float* src;
    if (n < NQK) {
        int h = n >> 6, d = n & 63;
        src = Wq + ((size_t)h * EE + e) * DD + d;
    } else if (n < 2 * NQK) {
        int nn = n - NQK;
        int h = nn >> 6, d = nn & 63;
        src = Wk + ((size_t)h * EE + e) * DD + d;
    } else {
        int nn = n - 2 * NQK;
        int h = nn >> 4, r = nn & 15;
        src = Wvd + ((size_t)h * EE + e) * RR + r;
    }
    float4 f0 = *(const float4*)src;
    float4 f1 = *(const float4*)(src + 4);
    uint4 u;
    u.x = f16x2(f0.y, f0.x);
    u.y = f16x2(f0.w, f0.z);
    u.z = f16x2(f1.y, f1.x);
    u.w = f16x2(f1.w, f1.z);
    *(uint4*)(g_Wh + (size_t)e * NTOT + n) = u;

    if (t8 < NTOT / 8) {
        int nb = t8 * 8;
        const float* bs;
        if (nb < NQK)          bs = bq + nb;
        else if (nb < 2 * NQK) bs = bk + (nb - NQK);
        else                   bs = bvd + (nb - 2 * NQK);
        float4 b0 = *(const float4*)bs;
        float4 b1 = *(const float4*)(bs + 4);
        *(float4*)(g_ball + nb)     = b0;
        *(float4*)(g_ball + nb + 4) = b1;
    }
}

// ---------------- fused QKV projection GEMM (fp16 m16n8k16) ----------------
#define AH 24
#define BW 9
__global__ void __launch_bounds__(256) qkv_gemm_kernel() {
    __shared__ __half   As[2][128 * AH];
    __shared__ uint32_t Bs[2][128 * BW];

    const int m0 = blockIdx.y * 128;
    const int n0 = blockIdx.x * 128;
    const int tid = threadIdx.x;
    const int lane = tid & 31;
    const int warp = tid >> 5;
    const int lg = lane >> 2;
    const int lr = lane & 3;
    const int wm = (warp >> 2) * 64;
    const int wn = (warp & 3) * 32;

    const int am = tid >> 1;
    const int ak = (tid & 1) * 8;
    const int bk2 = tid & 7;
    const int bn = (tid >> 3) * 8;

    const uint32_t asbase = (uint32_t)__cvta_generic_to_shared(&As[0][0]);
    const uint32_t laneoff_a = (uint32_t)(((lane & 7) + ((lane >> 3) & 1) * 8) * (AH * 2) + (lane >> 4) * 16);

    float c[4][4][4];
#pragma unroll
    for (int i = 0; i < 4; ++i)
#pragma unroll
        for (int j = 0; j < 4; ++j)
#pragma unroll
            for (int e = 0; e < 4; ++e) c[i][j][e] = 0.f;

    uint4 pa, pb0, pb1;
    pa = *(const uint4*)(g_Xh + (size_t)(m0 + am) * EE + ak);
    if (tid < 128) {
        pb0 = *(const uint4*)(g_Wh + (size_t)(2 * bk2) * NTOT + n0 + bn);
        pb1 = *(const uint4*)(g_Wh + (size_t)(2 * bk2 + 1) * NTOT + n0 + bn);
    }
    {
        *(uint4*)(&As[0][am * AH + ak]) = pa;
        if (tid < 128) {
            uint32_t* bdst = &Bs[0][0];
            bdst[(bn + 0) * BW + bk2] = prmt(pb0.x, pb1.x, 0x5410);
            bdst[(bn + 1) * BW + bk2] = prmt(pb0.x, pb1.x, 0x7632);
            bdst[(bn + 2) * BW + bk2] = prmt(pb0.y, pb1.y, 0x5410);
            bdst[(bn + 3) * BW + bk2] = prmt(pb0.y, pb1.y, 0x7632);
            bdst[(bn + 4) * BW + bk2] = prmt(pb0.z, pb1.z, 0x5410);
            bdst[(bn + 5) * BW + bk2] = prmt(pb0.z, pb1.z, 0x7632);
            bdst[(bn + 6) * BW + bk2] = prmt(pb0.w, pb1.w, 0x5410);
            bdst[(bn + 7) * BW + bk2] = prmt(pb0.w, pb1.w, 0x7632);
        }
    }
    __syncthreads();

    const int NK = EE / 16;
    for (int kt = 0; kt < NK; ++kt) {
        const int cur = kt & 1;
        if (kt + 1 < NK) {
            int k0 = (kt + 1) * 16;
            pa = *(const uint4*)(g_Xh + (size_t)(m0 + am) * EE + k0 + ak);
            if (tid < 128) {
                pb0 = *(const uint4*)(g_Wh + (size_t)(k0 + 2 * bk2) * NTOT + n0 + bn);
                pb1 = *(const uint4*)(g_Wh + (size_t)(k0 + 2 * bk2 + 1) * NTOT + n0 + bn);
            }
        }

        uint32_t a[4][4];
#pragma unroll
        for (int mt = 0; mt < 4; ++mt) {
            uint32_t aaddr = asbase + (uint32_t)(cur * 128 * AH * 2)
                           + (uint32_t)((wm + mt * 16) * (AH * 2)) + laneoff_a;
            ldsm4(a[mt][0], a[mt][1], a[mt][2], a[mt][3], aaddr);
        }
        uint32_t b[4][2];
#pragma unroll
        for (int nt = 0; nt < 4; ++nt) {
            int col = wn + nt * 8 + lg;
            b[nt][0] = Bs[cur][col * BW + lr];
            b[nt][1] = Bs[cur][col * BW + lr + 4];
        }
#pragma unroll
        for (int mt = 0; mt < 4; ++mt)
#pragma unroll
            for (int nt = 0; nt < 4; ++nt)
                mma_f16(c[mt][nt], a[mt], b[nt][0], b[nt][1]);

        if (kt + 1 < NK) {
            int nxt = cur ^ 1;
            *(uint4*)(&As[nxt][am * AH + ak]) = pa;
            if (tid < 128) {
                uint32_t* bdst = &Bs[nxt][0];
                bdst[(bn + 0) * BW + bk2] = prmt(pb0.x, pb1.x, 0x5410);
                bdst[(bn + 1) * BW + bk2] = prmt(pb0.x, pb1.x, 0x7632);
                bdst[(bn + 2) * BW + bk2] = prmt(pb0.y, pb1.y, 0x5410);
                bdst[(bn + 3) * BW + bk2] = prmt(pb0.y, pb1.y, 0x7632);
                bdst[(bn + 4) * BW + bk2] = prmt(pb0.z, pb1.z, 0x5410);
                bdst[(bn + 5) * BW + bk2] = prmt(pb0.z, pb1.z, 0x7632);
                bdst[(bn + 6) * BW + bk2] = prmt(pb0.w, pb1.w, 0x5410);
                bdst[(bn + 7) * BW + bk2] = prmt(pb0.w, pb1.w, 0x7632);
            }
        }
        __syncthreads();
    }

#pragma unroll
    for (int mt = 0; mt < 4; ++mt) {
#pragma unroll
        for (int e2 = 0; e2 < 2; ++e2) {
            int m = m0 + wm + mt * 16 + lg + e2 * 8;
            int b_ = m >> 11;
            int s = m & 2047;
#pragma unroll
            for (int nt = 0; nt < 4; ++nt) {
                int n = n0 + wn + nt * 8 + 2 * lr;
                float2 bias = *(const float2*)(g_ball + n);
                float vx = c[mt][nt][e2 * 2 + 0] + bias.x;
                float vy = c[mt][nt][e2 * 2 + 1] + bias.y;
                if (n < NQK) {
                    int h = n >> 6, d = n & 63;
                    uint32_t w = f16x2(vy * QSCALE, vx * QSCALE);
                    *(uint32_t*)(g_qh + (((size_t)(b_ * HH + h)) * SS + s) * DD + d) = w;
                } else if (n < 2 * NQK) {
                    int nn = n - NQK;
                    int h = nn >> 6, d = nn & 63;
                    uint32_t w = f16x2(vy, vx);
                    *(uint32_t*)(g_kh + (((size_t)(b_ * HH + h)) * SS + s) * DD + d) = w;
                } else {
                    int nn = n - 2 * NQK;
                    int h = nn >> 4, r = nn & 15;
                    uint32_t w = f16x2(vy, vx);
                    *(uint32_t*)(g_vdh + (((size_t)(b_ * HH + h)) * SS + s) * RR + r) = w;
                }
            }
        }
    }
}

// ---------------- V up-projection -> fp16 (2 rows x 4 d per thread) ----------------
__global__ void __launch_bounds__(256) vu_kernel(const float* __restrict__ Wvu,
                                                 const float* __restrict__ bvu) {
    const int tid = threadIdx.x;
    const int pairIdx = blockIdx.x * 16 + (tid >> 4);
    const int g0 = pairIdx * 2;
    const int dx = (tid & 15) * 4;
    const int h = (g0 >> 11) & 15;

    const float* w = Wvu + (size_t)h * RR * DD + dx;
    const __half2* vd0p = (const __half2*)(g_vdh + (size_t)g0 * RR);

    float vr0[RR], vr1[RR];
#pragma unroll
    for (int i = 0; i < 8; ++i) {
        float2 f0 = __half22float2(vd0p[i]);
        float2 f1 = __half22float2(vd0p[8 + i]);
        vr0[2 * i] = f0.x; vr0[2 * i + 1] = f0.y;
        vr1[2 * i] = f1.x; vr1[2 * i + 1] = f1.y;
    }

    float4 b4 = *(const float4*)(bvu + h * DD + dx);
    float4 a0 = b4, a1 = b4;
#pragma unroll
    for (int r = 0; r < RR; ++r) {
        float4 w4 = *(const float4*)(w + r * DD);
        a0.x += vr0[r] * w4.x; a0.y += vr0[r] * w4.y;
        a0.z += vr0[r] * w4.z; a0.w += vr0[r] * w4.w;
        a1.x += vr1[r] * w4.x; a1.y += vr1[r] * w4.y;
        a1.z += vr1[r] * w4.z; a1.w += vr1[r] * w4.w;
    }
    uint2 o0 = make_uint2(f16x2(a0.y, a0.x), f16x2(a0.w, a0.z));
    uint2 o1 = make_uint2(f16x2(a1.y, a1.x), f16x2(a1.w, a1.z));
    *(uint2*)(g_vh + (size_t)g0 * DD + dx)       = o0;
    *(uint2*)(g_vh + (size_t)(g0 + 1) * DD + dx) = o1;
}

// ---------------- flash attention: 128q per block, 8 warps, shared K/V ----------------
#define KVH 72
#define KVBYTES (64 * KVH * 2)
__global__ void __launch_bounds__(256) attn_kernel(float* __restrict__ out) {
    __shared__ __half Ks[2][64 * KVH];
    __shared__ __half Vs[2][64 * KVH];

    const int qt = blockIdx.x;          // 0..15 (128-row q blocks)
    const int bh = blockIdx.y;
    const __half* qb = g_qh + (size_t)bh * SS * DD;
    const __half* kb = g_kh + (size_t)bh * SS * DD;
    const __half* vb = g_vh + (size_t)bh * SS * DD;

    const int tid = threadIdx.x;
    const int lane = tid & 31;
    const int warp = tid >> 5;
    const int wg = warp >> 2;           // q-subtile 0/1
    const int wl = warp & 3;            // warp within subtile
    const int lg = lane >> 2;
    const int lr = lane & 3;

    const int q0w = qt * 128 + wg * 64; // this warp-group's q base

    const uint32_t ksbase = (uint32_t)__cvta_generic_to_shared(&Ks[0][0]);
    const uint32_t vsbase = (uint32_t)__cvta_generic_to_shared(&Vs[0][0]);
    const uint32_t laneoff_q = (uint32_t)(((lane & 7) + ((lane >> 3) & 1) * 8) * (KVH * 2) + (lane >> 4) * 16);
    const uint32_t laneoff_k = (uint32_t)((lane & 7) * (KVH * 2) + (lane >> 3) * 16);

    const int NT = SS / 64;
    const int tstart = 2 * qt;

    // issue async load of kv tile t into buffer buf
    auto issue_tile = [&](int buf, int t) {
        const __half* kbase = kb + (size_t)t * 64 * DD;
        const __half* vbase = vb + (size_t)t * 64 * DD;
        uint32_t kdst = ksbase + buf * KVBYTES;
        uint32_t vdst = vsbase + buf * KVBYTES;
#pragma unroll
        for (int it = 0; it < 2; ++it) {
            int idx = tid + it * 256;
            int r = idx >> 3;
            int c8 = (idx & 7) * 8;
            cp16(kdst + r * (KVH * 2) + c8 * 2, kbase + r * DD + c8);
            cp16(vdst + r * (KVH * 2) + c8 * 2, vbase + r * DD + c8);
        }
    };

    // prologue: async-load first tile into buf 0; stage 128 Q rows in Ks[1]/Vs[1]
    issue_tile(0, tstart);
    CP_COMMIT();

#pragma unroll
    for (int it = 0; it < 4; ++it) {
        int idx = tid + it * 256;       // 1024 slots: 128 rows x 8 chunks
        int r = idx >> 3;
        int c8 = (idx & 7) * 8;
        __half* dst = (r < 64) ? &Ks[1][r * KVH + c8] : &Vs[1][(r - 64) * KVH + c8];
        *(uint4*)dst = *(const uint4*)(qb + (size_t)(qt * 128 + r) * DD + c8);
    }
    __syncthreads();

    uint32_t aq[4][4];
    {
        uint32_t qa = (wg ? vsbase : ksbase) + KVBYTES + (uint32_t)(wl * 16 * (KVH * 2)) + laneoff_q;
#pragma unroll
        for (int kc = 0; kc < 4; ++kc)
            ldsm4(aq[kc][0], aq[kc][1], aq[kc][2], aq[kc][3], qa + kc * 32);
    }
    __syncthreads();

    float o[8][4];
    float m0r = -1e30f, m1r = -1e30f, l0r = 0.f, l1r = 0.f;
#pragma unroll
    for (int j = 0; j < 8; ++j)
#pragma unroll
        for (int e = 0; e < 4; ++e) o[j][e] = 0.f;

    for (int t = tstart; t < NT; ++t) {
        const int cur = (t - tstart) & 1;
        if (t + 1 < NT) {
            issue_tile(cur ^ 1, t + 1);
            CP_COMMIT();
            CP_WAIT1();
        } else {
            CP_WAIT0();
        }
        __syncthreads();

        if (t >= tstart + wg) {   // skip fully-masked tile for subtile B
            const uint32_t kcur = ksbase + cur * KVBYTES;
            const uint32_t vcur = vsbase + cur * KVBYTES;

            // ---- S = Q @ K^T ----
            float s[8][4];
#pragma unroll
            for (int j = 0; j < 8; ++j)
#pragma unroll
                for (int e = 0; e < 4; ++e) s[j][e] = 0.f;

#pragma unroll
            for (int j = 0; j < 8; ++j) {
                uint32_t kaddr = kcur + (uint32_t)(j * 8 * (KVH * 2)) + laneoff_k;
#pragma unroll
                for (int kcp = 0; kcp < 2; ++kcp) {
                    uint32_t r0, r1, r2, r3;
                    ldsm4(r0, r1, r2, r3, kaddr + kcp * 64);
                    mma_f16(s[j], aq[2 * kcp], r0, r1);
                    mma_f16(s[j], aq[2 * kcp + 1], r2, r3);
                }
            }

            // ---- reverse-causal mask (diagonal tile of this subtile) ----
            if (t == tstart + wg) {
                int qr0 = q0w + wl * 16 + lg;
#pragma unroll
                for (int j = 0; j < 8; ++j) {
                    int kg = t * 64 + j * 8 + lr * 2;
                    if (kg < qr0)          s[j][0] = -1e30f;
                    if (kg + 1 < qr0)      s[j][1] = -1e30f;
                    if (kg < qr0 + 8)      s[j][2] = -1e30f;
                    if (kg + 1 < qr0 + 8)  s[j][3] = -1e30f;
                }
            }

            // ---- online softmax (base-2) ----
            float rm0 = -1e30f, rm1 = -1e30f;
#pragma unroll
            for (int j = 0; j < 8; ++j) {
                rm0 = fmaxf(rm0, fmaxf(s[j][0], s[j][1]));
                rm1 = fmaxf(rm1, fmaxf(s[j][2], s[j][3]));
            }
            rm0 = fmaxf(rm0, __shfl_xor_sync(0xffffffffu, rm0, 1));
            rm0 = fmaxf(rm0, __shfl_xor_sync(0xffffffffu, rm0, 2));
            rm1 = fmaxf(rm1, __shfl_xor_sync(0xffffffffu, rm1, 1));
            rm1 = fmaxf(rm1, __shfl_xor_sync(0xffffffffu, rm1, 2));

            float mn0 = fmaxf(m0r, rm0);
            float mn1 = fmaxf(m1r, rm1);
            float al0 = ex2(m0r - mn0);
            float al1 = ex2(m1r - mn1);
            m0r = mn0; m1r = mn1;

            float rs0 = 0.f, rs1 = 0.f;
            uint32_t p2[8][2];
#pragma unroll
            for (int j = 0; j < 8; ++j) {
                float p0 = ex2(s[j][0] - mn0);
                float p1 = ex2(s[j][1] - mn0);
                float p2v = ex2(s[j][2] - mn1);
                float p3 = ex2(s[j][3] - mn1);
                rs0 += p0 + p1;
                rs1 += p2v + p3;
                p2[j][0] = f16x2(p1, p0);
                p2[j][1] = f16x2(p3, p2v);
            }
            rs0 += __shfl_xor_sync(0xffffffffu, rs0, 1);
            rs0 += __shfl_xor_sync(0xffffffffu, rs0, 2);
            rs1 += __shfl_xor_sync(0xffffffffu, rs1, 1);
            rs1 += __shfl_xor_sync(0xffffffffu, rs1, 2);
            l0r = l0r * al0 + rs0;
            l1r = l1r * al1 + rs1;

#pragma unroll
            for (int j = 0; j < 8; ++j) {
                o[j][0] *= al0; o[j][1] *= al0;
                o[j][2] *= al1; o[j][3] *= al1;
            }

            // ---- O += P @ V ----
#pragma unroll
            for (int g = 0; g < 4; ++g) {
                uint32_t a[4];
                a[0] = p2[2 * g][0];
                a[1] = p2[2 * g][1];
                a[2] = p2[2 * g + 1][0];
                a[3] = p2[2 * g + 1][1];
                uint32_t vaddr = vcur + (uint32_t)(g * 16 * (KVH * 2)) + laneoff_q;
#pragma unroll
                for (int dp = 0; dp < 4; ++dp) {
                    uint32_t r0, r1, r2, r3;
                    ldsm4t(r0, r1, r2, r3, vaddr + dp * 32);
                    mma_f16(o[2 * dp], a, r0, r1);
                    mma_f16(o[2 * dp + 1], a, r2, r3);
                }
            }
        }
        __syncthreads();
    }

    // ---- write normalized output ----
    int h = bh % HH, b = bh / HH;
    float inv0 = 1.f / l0r;
    float inv1 = 1.f / l1r;
    int qr0 = q0w + wl * 16 + lg;
#pragma unroll
    for (int j2 = 0; j2 < 8; ++j2) {
        int d = j2 * 8 + lr * 2;
        float2 v0 = make_float2(o[j2][0] * inv0, o[j2][1] * inv0);
        float2 v1 = make_float2(o[j2][2] * inv1, o[j2][3] * inv1);
        *(float2*)(out + (((size_t)(b * SS + qr0)) * HH + h) * DD + d) = v0;
        *(float2*)(out + (((size_t)(b * SS + qr0 + 8)) * HH + h) * DD + d) = v1;
    }
}

// ---------------- launcher ----------------
extern "C" void kernel_launch(void* const* d_in, const int* in_sizes, int n_in,
                              void* d_out, int out_size) {
    const float* x   = (const float*)d_in[0];
    const float* Wq  = (const float*)d_in[1];
    const float* bq  = (const float*)d_in[2];
    const float* Wk  = (const float*)d_in[3];
    const float* bk  = (const float*)d_in[4];
    const float* Wvd = (const float*)d_in[5];
    const float* bvd = (const float*)d_in[6];
    const float* Wvu = (const float*)d_in[7];
    const float* bvu = (const float*)d_in[8];
    float* out = (float*)d_out;

    {
        int n8 = MROWS * EE / 8;
        xh_kernel<<<n8 / 256, 256>>>(x);
    }
    {
        int t8 = EE * NTOT / 8;
        pack_kernel<<<t8 / 256, 256>>>(Wq, bq, Wk, bk, Wvd, bvd);
    }
    {
        dim3 grid(NTOT / 128, MROWS / 128);  // (18, 32)
        qkv_gemm_kernel<<<grid, 256>>>();
    }
    {
        vu_kernel<<<(BH * SS) / 32, 256>>>(Wvu, bvu);
    }
    {
        dim3 grid(SS / 128, BH);  // (16, 32)
        attn_kernel<<<grid, 256>>>(out);
    }
}